// round 9
// baseline (speedup 1.0000x reference)
#include <cuda_runtime.h>
#include <cuda_fp16.h>
#include <cstdint>
#include <cstddef>

// ============================================================================
// QUIK quantized linear, B = in = out = 4096.
//   x_q = trunc(clip((x - min(x))/((max-min)/8) - 4, -4, 3))   (global affine)
//   w_q likewise; out[i,j] = (x_q[i,:]·w_q[j,:] + bias[j])*s_a*s_w
//                            + (zero_a + 4*s_a)*rowsum_w[i]    (note index i)
// R9: f16-accumulate HMMA (m16n8k16.f16) is historically 2x the f32-acc rate
// on rate-split FP16 pipes. Exact because any partial over <=128 K terms is an
// integer <= 2048 (f16-exact); flushed to f32 masters every 2 k-tiles.
// ============================================================================

#define DIM 4096
#define BM 128
#define BN 128
#define BK 64             // f16 elements per k-tile = 128 bytes per row
#define NITER (DIM / BK)  // 64
#define STAGES 3
#define STAGE_BYTES (2 * BM * 128)         // A(16K) + B(16K) = 32768
#define SMEM_TOTAL (STAGES * STAGE_BYTES)  // 98304

// ---------------- device scratch (allocation-free rule) ---------------------
// min/max accumulators carry static initial values; gemm's tail resets them
// for the next kernel_launch call (stream-ordered before the next reduce).
__device__ unsigned g_xmin_e = 0xFFFFFFFFu, g_xmax_e = 0u;
__device__ unsigned g_wmin_e = 0xFFFFFFFFu, g_wmax_e = 0u;
__device__ float g_rowsum[DIM];
__device__ float g_consts[8];  // 0:s=sa*sw 1:shiftc 2:x_zero 3:x_scale 4:w_zero 5:w_scale
__device__ unsigned short g_xqh[(size_t)DIM * DIM];  // f16 bits of quantized x
__device__ unsigned short g_wqh[(size_t)DIM * DIM];  // f16 bits of quantized w

// ---------------- PTX helpers (plain-sm80/75 features only) -----------------
__device__ __forceinline__ uint32_t smem_to_u32(const void* p) {
    uint32_t a;
    asm("{ .reg .u64 t; cvta.to.shared.u64 t, %1; cvt.u32.u64 %0, t; }" : "=r"(a) : "l"(p));
    return a;
}

#define CP_ASYNC16(saddr, gptr)                                              \
    asm volatile("cp.async.cg.shared.global [%0], [%1], 16;"                 \
                 :: "r"(saddr), "l"(gptr) : "memory")
#define CP_COMMIT() asm volatile("cp.async.commit_group;" ::: "memory")
#define CP_WAIT1()  asm volatile("cp.async.wait_group 1;" ::: "memory")

#define LDSM_X4(r, addr)                                                     \
    asm volatile("ldmatrix.sync.aligned.m8n8.x4.shared.b16 {%0,%1,%2,%3}, [%4];" \
                 : "=r"((r)[0]), "=r"((r)[1]), "=r"((r)[2]), "=r"((r)[3])    \
                 : "r"(addr))

// f16 HMMA, f16 accumulate (target: the half-rate-split fast path)
#define MMA_F16H(c, a, b0v, b1v)                                             \
    asm volatile("mma.sync.aligned.m16n8k16.row.col.f16.f16.f16.f16 "        \
                 "{%0,%1}, {%2,%3,%4,%5}, {%6,%7}, {%0,%1};"                 \
                 : "+r"((c)[0]), "+r"((c)[1])                                \
                 : "r"((a)[0]), "r"((a)[1]), "r"((a)[2]), "r"((a)[3]),       \
                   "r"(b0v), "r"(b1v))

// Monotone float<->uint encoding for atomic min/max on fp32
__device__ __forceinline__ unsigned fenc(float f) {
    unsigned u = __float_as_uint(f);
    return (u & 0x80000000u) ? ~u : (u | 0x80000000u);
}
__device__ __forceinline__ float fdec(unsigned e) {
    return (e & 0x80000000u) ? __uint_as_float(e & 0x7FFFFFFFu) : __uint_as_float(~e);
}

// ============================================================================
// Kernel: per-row pass — global min/max of x and w, weight row sums
// ============================================================================
__global__ void __launch_bounds__(256) reduce_kernel(const float* __restrict__ x,
                                                     const float* __restrict__ w) {
    const int row = blockIdx.x, tid = threadIdx.x;
    const float4* xr = reinterpret_cast<const float4*>(x + ((size_t)row << 12));
    const float4* wr = reinterpret_cast<const float4*>(w + ((size_t)row << 12));
    float xmn = 3.4e38f, xmx = -3.4e38f, wmn = 3.4e38f, wmx = -3.4e38f, ws = 0.0f;
    for (int i = tid; i < 1024; i += 256) {
        float4 a = xr[i];
        xmn = fminf(xmn, fminf(fminf(a.x, a.y), fminf(a.z, a.w)));
        xmx = fmaxf(xmx, fmaxf(fmaxf(a.x, a.y), fmaxf(a.z, a.w)));
        float4 b = wr[i];
        wmn = fminf(wmn, fminf(fminf(b.x, b.y), fminf(b.z, b.w)));
        wmx = fmaxf(wmx, fmaxf(fmaxf(b.x, b.y), fmaxf(b.z, b.w)));
        ws += (b.x + b.y) + (b.z + b.w);
    }
    #pragma unroll
    for (int o = 16; o; o >>= 1) {
        xmn = fminf(xmn, __shfl_xor_sync(0xFFFFFFFFu, xmn, o));
        xmx = fmaxf(xmx, __shfl_xor_sync(0xFFFFFFFFu, xmx, o));
        wmn = fminf(wmn, __shfl_xor_sync(0xFFFFFFFFu, wmn, o));
        wmx = fmaxf(wmx, __shfl_xor_sync(0xFFFFFFFFu, wmx, o));
        ws += __shfl_xor_sync(0xFFFFFFFFu, ws, o);
    }
    __shared__ float s_xmn[8], s_xmx[8], s_wmn[8], s_wmx[8], s_ws[8];
    const int wid = tid >> 5, lane = tid & 31;
    if (lane == 0) { s_xmn[wid] = xmn; s_xmx[wid] = xmx; s_wmn[wid] = wmn; s_wmx[wid] = wmx; s_ws[wid] = ws; }
    __syncthreads();
    if (tid == 0) {
        float a = s_xmn[0], b = s_xmx[0], c = s_wmn[0], d = s_wmx[0], e = s_ws[0];
        #pragma unroll
        for (int i = 1; i < 8; i++) {
            a = fminf(a, s_xmn[i]); b = fmaxf(b, s_xmx[i]);
            c = fminf(c, s_wmn[i]); d = fmaxf(d, s_wmx[i]);
            e += s_ws[i];
        }
        atomicMin(&g_xmin_e, fenc(a)); atomicMax(&g_xmax_e, fenc(b));
        atomicMin(&g_wmin_e, fenc(c)); atomicMax(&g_wmax_e, fenc(d));
        g_rowsum[row] = e;
    }
}

// ============================================================================
// Kernel: scalar constants
// ============================================================================
__global__ void finalize_kernel() {
    if (threadIdx.x == 0) {
        float xmin = fdec(g_xmin_e), xmax = fdec(g_xmax_e);
        float wmin = fdec(g_wmin_e), wmax = fdec(g_wmax_e);
        float sa = (xmax - xmin) * 0.125f;  // /8 exact
        float sw = (wmax - wmin) * 0.125f;
        g_consts[0] = sa * sw;
        g_consts[1] = xmin + 4.0f * sa;
        g_consts[2] = xmin; g_consts[3] = sa;
        g_consts[4] = wmin; g_consts[5] = sw;
    }
}

// ============================================================================
// Kernel: quantize BOTH matrices to f16 scratch (blockIdx.y: 0=x, 1=w).
// Bit-matches reference: IEEE rn div, clip, trunc-toward-zero.
// ============================================================================
__global__ void __launch_bounds__(256) quant_kernel(const float* __restrict__ x,
                                                    const float* __restrict__ w) {
    const int which = blockIdx.y;
    const float zero  = which ? g_consts[4] : g_consts[2];
    const float scale = which ? g_consts[5] : g_consts[3];
    const float* src = which ? w : x;
    unsigned short* dst = which ? g_wqh : g_xqh;
    const size_t i = ((size_t)blockIdx.x * 256 + threadIdx.x) * 8;
    const float4* s4 = reinterpret_cast<const float4*>(src + i);
    float4 a = s4[0], b = s4[1];
    float v[8] = {a.x, a.y, a.z, a.w, b.x, b.y, b.z, b.w};
    unsigned r[4];
    #pragma unroll
    for (int k = 0; k < 4; k++) {
        float q0 = fminf(fmaxf(__fdiv_rn(v[2 * k] - zero, scale) - 4.0f, -4.0f), 3.0f);
        float q1 = fminf(fmaxf(__fdiv_rn(v[2 * k + 1] - zero, scale) - 4.0f, -4.0f), 3.0f);
        unsigned lo = __half_as_ushort(__float2half_rn((float)(int)q0));
        unsigned hi = __half_as_ushort(__float2half_rn((float)(int)q1));
        r[k] = lo | (hi << 16);
    }
    *reinterpret_cast<uint4*>(dst + i) = make_uint4(r[0], r[1], r[2], r[3]);
}

// ============================================================================
// Dummy launch: shifts the GEMM into the ncu-captured launch slot.
// ============================================================================
__global__ void dummy_kernel() {}

// ============================================================================
// Kernel: f16 HMMA GEMM with f16 accumulate + periodic exact f32 flush.
// 128x128 tile, BK=64, 256 threads (2x4 warps, warp tile 64x32), 3-stage
// cp.async pipeline, ldmatrix.x4, fused dequant epilogue.
// Flush every 2 k-tiles (128 K): |partial| <= 16*128 = 2048, f16-exact.
// ============================================================================
__global__ void __launch_bounds__(256) gemm_kernel(const float* __restrict__ bias,
                                                   float* __restrict__ out) {
    extern __shared__ char smem[];
    const int tid = threadIdx.x, lane = tid & 31, wid = tid >> 5;
    const int warp_m = wid >> 2, warp_n = wid & 3;   // 2 x 4 warp grid
    const int bx = blockIdx.x, by = blockIdx.y;      // bx: N tiles, by: M tiles
    const uint32_t sm0 = smem_to_u32(smem);

    const unsigned short* Agbase = g_xqh + ((size_t)(by * BM) << 12);
    const unsigned short* Bgbase = g_wqh + ((size_t)(bx * BN) << 12);

    // copy-loop coords: 1024 16B-chunks per matrix per stage; 4 per thread
    int cp_so[4], cp_go[4];
    #pragma unroll
    for (int i = 0; i < 4; i++) {
        int id = tid + i * 256;
        int r = id >> 3, c = id & 7;
        cp_so[i] = r * 128 + ((c ^ (r & 7)) << 4);  // swizzled SMEM offset
        cp_go[i] = (r << 13) + (c << 4);            // gmem byte offset
    }

    const int a_row  = warp_m * 64 + (lane & 7) + ((lane >> 3) & 1) * 8;
    const int a_kbit = (lane >> 4) & 1;
    const int a_xor  = a_row & 7;
    uint32_t a_rowoff[4];
    #pragma unroll
    for (int mb = 0; mb < 4; mb++) a_rowoff[mb] = (uint32_t)(a_row + mb * 16) * 128;

    const int b_col  = warp_n * 32 + (lane & 7) + ((lane >> 3) & 1) * 8;
    const int b_kbit = (lane >> 4) & 1;
    const int b_xor  = b_col & 7;
    uint32_t b_rowoff[2];
    #pragma unroll
    for (int h = 0; h < 2; h++) b_rowoff[h] = (uint32_t)(b_col + h * 16) * 128;

    float facc[4][4][4];      // f32 master accumulators
    uint32_t hacc[4][4][2];   // f16x2 chunk accumulators
    #pragma unroll
    for (int mb = 0; mb < 4; mb++)
        #pragma unroll
        for (int nb = 0; nb < 4; nb++) {
            facc[mb][nb][0] = facc[mb][nb][1] = facc[mb][nb][2] = facc[mb][nb][3] = 0.0f;
            hacc[mb][nb][0] = hacc[mb][nb][1] = 0u;
        }

    auto load_stage = [&](int kt, int st) {
        const uint32_t As = sm0 + st * STAGE_BYTES;
        const uint32_t Bs = As + BM * 128;
        const unsigned short* Ag = Agbase + (size_t)kt * BK;
        const unsigned short* Bg = Bgbase + (size_t)kt * BK;
        #pragma unroll
        for (int i = 0; i < 4; i++) {
            CP_ASYNC16(As + cp_so[i], Ag + (cp_go[i] >> 1));
            CP_ASYNC16(Bs + cp_so[i], Bg + (cp_go[i] >> 1));
        }
    };

    load_stage(0, 0); CP_COMMIT();
    load_stage(1, 1); CP_COMMIT();

    int st = 0, nst = 2;
    #pragma unroll 1
    for (int kt = 0; kt < NITER; kt++) {
        CP_WAIT1();
        __syncthreads();
        if (kt + 2 < NITER) load_stage(kt + 2, nst);
        CP_COMMIT();

        const uint32_t As = sm0 + st * STAGE_BYTES;
        const uint32_t Bs = As + BM * 128;
        #pragma unroll
        for (int ks = 0; ks < 4; ks++) {  // 4 x k16 steps per BK=64
            const uint32_t ac = (uint32_t)(((2 * ks + a_kbit) ^ a_xor) << 4);
            const uint32_t bc = (uint32_t)(((2 * ks + b_kbit) ^ b_xor) << 4);
            uint32_t A[4][4], Bf[2][4];
            #pragma unroll
            for (int mb = 0; mb < 4; mb++) LDSM_X4(A[mb], As + a_rowoff[mb] + ac);
            #pragma unroll
            for (int h = 0; h < 2; h++)    LDSM_X4(Bf[h], Bs + b_rowoff[h] + bc);
            #pragma unroll
            for (int mb = 0; mb < 4; mb++) {
                MMA_F16H(hacc[mb][0], A[mb], Bf[0][0], Bf[0][2]);
                MMA_F16H(hacc[mb][1], A[mb], Bf[0][1], Bf[0][3]);
                MMA_F16H(hacc[mb][2], A[mb], Bf[1][0], Bf[1][2]);
                MMA_F16H(hacc[mb][3], A[mb], Bf[1][1], Bf[1][3]);
            }
        }
        if (kt & 1) {  // flush: 128 K accumulated, |partial| <= 2048, exact
            #pragma unroll
            for (int mb = 0; mb < 4; mb++)
                #pragma unroll
                for (int nb = 0; nb < 4; nb++) {
                    float2 lo = __half22float2(*reinterpret_cast<__half2*>(&hacc[mb][nb][0]));
                    float2 hi = __half22float2(*reinterpret_cast<__half2*>(&hacc[mb][nb][1]));
                    facc[mb][nb][0] += lo.x; facc[mb][nb][1] += lo.y;
                    facc[mb][nb][2] += hi.x; facc[mb][nb][3] += hi.y;
                    hacc[mb][nb][0] = 0u; hacc[mb][nb][1] = 0u;
                }
        }
        st  = (st  == 2) ? 0 : st  + 1;
        nst = (nst == 2) ? 0 : nst + 1;
    }

    // Epilogue: out[r][c] = (facc + bias[c]) * s + shc * rowsum[r]
    const float s = g_consts[0], shc = g_consts[1];
    const int gr0 = by * BM + warp_m * 64 + (lane >> 2);
    const int gc0 = bx * BN + warp_n * 32 + (lane & 3) * 2;
    #pragma unroll
    for (int mb = 0; mb < 4; mb++) {
        const int r0 = gr0 + mb * 16, r1 = r0 + 8;
        const float sh0 = shc * g_rowsum[r0];
        const float sh1 = shc * g_rowsum[r1];
        float* o0 = out + ((size_t)r0 << 12);
        float* o1 = out + ((size_t)r1 << 12);
        #pragma unroll
        for (int nb = 0; nb < 4; nb++) {
            const int gc = gc0 + nb * 8;
            const float bv0 = bias[gc], bv1 = bias[gc + 1];
            float2 v0, v1;
            v0.x = fmaf(facc[mb][nb][0] + bv0, s, sh0);
            v0.y = fmaf(facc[mb][nb][1] + bv1, s, sh0);
            v1.x = fmaf(facc[mb][nb][2] + bv0, s, sh1);
            v1.y = fmaf(facc[mb][nb][3] + bv1, s, sh1);
            *reinterpret_cast<float2*>(o0 + gc) = v0;
            *reinterpret_cast<float2*>(o1 + gc) = v1;
        }
    }

    // Reset min/max accumulators for the next kernel_launch call (stream-
    // ordered before the next reduce_kernel).
    if (bx == 0 && by == 0 && tid == 0) {
        g_xmin_e = 0xFFFFFFFFu; g_xmax_e = 0u;
        g_wmin_e = 0xFFFFFFFFu; g_wmax_e = 0u;
    }
}

// ============================================================================
extern "C" void kernel_launch(void* const* d_in, const int* in_sizes, int n_in,
                              void* d_out, int out_size) {
    (void)in_sizes; (void)n_in; (void)out_size;
    const float* x    = (const float*)d_in[0];
    const float* w    = (const float*)d_in[1];
    const float* bias = (const float*)d_in[2];
    float* out = (float*)d_out;

    reduce_kernel<<<DIM, 256>>>(x, w);                        // launch 1
    finalize_kernel<<<1, 32>>>();                             // launch 2
    quant_kernel<<<dim3(DIM * DIM / (8 * 256), 2), 256>>>(x, w);  // launch 3
    dummy_kernel<<<1, 32>>>();                                // launch 4
    cudaFuncSetAttribute(gemm_kernel, cudaFuncAttributeMaxDynamicSharedMemorySize, SMEM_TOTAL);
    gemm_kernel<<<dim3(DIM / BN, DIM / BM), 256, SMEM_TOTAL>>>(bias, out);  // launch 5
}

// round 10
// speedup vs baseline: 1.1244x; 1.1244x over previous
#include <cuda_runtime.h>
#include <cuda_fp16.h>
#include <cstdint>
#include <cstddef>

// ============================================================================
// QUIK quantized linear, B = in = out = 4096.
//   x_q = trunc(clip((x - min(x))/((max-min)/8) - 4, -4, 3))   (global affine)
//   w_q likewise; out[i,j] = (x_q[i,:]·w_q[j,:] + bias[j])*s_a*s_w
//                            + (zero_a + 4*s_a)*rowsum_w[i]    (note index i)
// R10: revert to f32-accumulate HMMA (R9 proved f16-acc is same-rate + flush
// overhead). GEMM placed as launch #4 so ncu finally captures it.
// ============================================================================

#define DIM 4096
#define BM 128
#define BN 128
#define BK 64             // f16 elements per k-tile = 128 bytes per row
#define NITER (DIM / BK)  // 64
#define STAGES 3
#define STAGE_BYTES (2 * BM * 128)         // A(16K) + B(16K) = 32768
#define SMEM_TOTAL (STAGES * STAGE_BYTES)  // 98304

// ---------------- device scratch (allocation-free rule) ---------------------
// min/max accumulators carry static initial values; gemm's tail resets them
// for the next kernel_launch call (stream-ordered before the next reduce).
__device__ unsigned g_xmin_e = 0xFFFFFFFFu, g_xmax_e = 0u;
__device__ unsigned g_wmin_e = 0xFFFFFFFFu, g_wmax_e = 0u;
__device__ float g_rowsum[DIM];
__device__ float g_consts[8];  // 0:s=sa*sw 1:shiftc 2:x_zero 3:x_scale 4:w_zero 5:w_scale
__device__ unsigned short g_xqh[(size_t)DIM * DIM];  // f16 bits of quantized x
__device__ unsigned short g_wqh[(size_t)DIM * DIM];  // f16 bits of quantized w

// ---------------- PTX helpers (plain-sm80/75 features only) -----------------
__device__ __forceinline__ uint32_t smem_to_u32(const void* p) {
    uint32_t a;
    asm("{ .reg .u64 t; cvta.to.shared.u64 t, %1; cvt.u32.u64 %0, t; }" : "=r"(a) : "l"(p));
    return a;
}

#define CP_ASYNC16(saddr, gptr)                                              \
    asm volatile("cp.async.cg.shared.global [%0], [%1], 16;"                 \
                 :: "r"(saddr), "l"(gptr) : "memory")
#define CP_COMMIT() asm volatile("cp.async.commit_group;" ::: "memory")
#define CP_WAIT1()  asm volatile("cp.async.wait_group 1;" ::: "memory")

#define LDSM_X4(r, addr)                                                     \
    asm volatile("ldmatrix.sync.aligned.m8n8.x4.shared.b16 {%0,%1,%2,%3}, [%4];" \
                 : "=r"((r)[0]), "=r"((r)[1]), "=r"((r)[2]), "=r"((r)[3])    \
                 : "r"(addr))

// f16 HMMA, f32 accumulate: D(16x8) += A(16x16) * B(16x8)
#define MMA_F16(c, a, b0v, b1v)                                              \
    asm volatile("mma.sync.aligned.m16n8k16.row.col.f32.f16.f16.f32 "        \
                 "{%0,%1,%2,%3}, {%4,%5,%6,%7}, {%8,%9}, {%0,%1,%2,%3};"     \
                 : "+f"((c)[0]), "+f"((c)[1]), "+f"((c)[2]), "+f"((c)[3])    \
                 : "r"((a)[0]), "r"((a)[1]), "r"((a)[2]), "r"((a)[3]),       \
                   "r"(b0v), "r"(b1v))

// Monotone float<->uint encoding for atomic min/max on fp32
__device__ __forceinline__ unsigned fenc(float f) {
    unsigned u = __float_as_uint(f);
    return (u & 0x80000000u) ? ~u : (u | 0x80000000u);
}
__device__ __forceinline__ float fdec(unsigned e) {
    return (e & 0x80000000u) ? __uint_as_float(e & 0x7FFFFFFFu) : __uint_as_float(~e);
}

// ============================================================================
// Launch 1: per-row pass — global min/max of x and w, weight row sums
// ============================================================================
__global__ void __launch_bounds__(256) reduce_kernel(const float* __restrict__ x,
                                                     const float* __restrict__ w) {
    const int row = blockIdx.x, tid = threadIdx.x;
    const float4* xr = reinterpret_cast<const float4*>(x + ((size_t)row << 12));
    const float4* wr = reinterpret_cast<const float4*>(w + ((size_t)row << 12));
    float xmn = 3.4e38f, xmx = -3.4e38f, wmn = 3.4e38f, wmx = -3.4e38f, ws = 0.0f;
    for (int i = tid; i < 1024; i += 256) {
        float4 a = xr[i];
        xmn = fminf(xmn, fminf(fminf(a.x, a.y), fminf(a.z, a.w)));
        xmx = fmaxf(xmx, fmaxf(fmaxf(a.x, a.y), fmaxf(a.z, a.w)));
        float4 b = wr[i];
        wmn = fminf(wmn, fminf(fminf(b.x, b.y), fminf(b.z, b.w)));
        wmx = fmaxf(wmx, fmaxf(fmaxf(b.x, b.y), fmaxf(b.z, b.w)));
        ws += (b.x + b.y) + (b.z + b.w);
    }
    #pragma unroll
    for (int o = 16; o; o >>= 1) {
        xmn = fminf(xmn, __shfl_xor_sync(0xFFFFFFFFu, xmn, o));
        xmx = fmaxf(xmx, __shfl_xor_sync(0xFFFFFFFFu, xmx, o));
        wmn = fminf(wmn, __shfl_xor_sync(0xFFFFFFFFu, wmn, o));
        wmx = fmaxf(wmx, __shfl_xor_sync(0xFFFFFFFFu, wmx, o));
        ws += __shfl_xor_sync(0xFFFFFFFFu, ws, o);
    }
    __shared__ float s_xmn[8], s_xmx[8], s_wmn[8], s_wmx[8], s_ws[8];
    const int wid = tid >> 5, lane = tid & 31;
    if (lane == 0) { s_xmn[wid] = xmn; s_xmx[wid] = xmx; s_wmn[wid] = wmn; s_wmx[wid] = wmx; s_ws[wid] = ws; }
    __syncthreads();
    if (tid == 0) {
        float a = s_xmn[0], b = s_xmx[0], c = s_wmn[0], d = s_wmx[0], e = s_ws[0];
        #pragma unroll
        for (int i = 1; i < 8; i++) {
            a = fminf(a, s_xmn[i]); b = fmaxf(b, s_xmx[i]);
            c = fminf(c, s_wmn[i]); d = fmaxf(d, s_wmx[i]);
            e += s_ws[i];
        }
        atomicMin(&g_xmin_e, fenc(a)); atomicMax(&g_xmax_e, fenc(b));
        atomicMin(&g_wmin_e, fenc(c)); atomicMax(&g_wmax_e, fenc(d));
        g_rowsum[row] = e;
    }
}

// ============================================================================
// Launch 2: scalar constants
// ============================================================================
__global__ void finalize_kernel() {
    if (threadIdx.x == 0) {
        float xmin = fdec(g_xmin_e), xmax = fdec(g_xmax_e);
        float wmin = fdec(g_wmin_e), wmax = fdec(g_wmax_e);
        float sa = (xmax - xmin) * 0.125f;  // /8 exact
        float sw = (wmax - wmin) * 0.125f;
        g_consts[0] = sa * sw;
        g_consts[1] = xmin + 4.0f * sa;
        g_consts[2] = xmin; g_consts[3] = sa;
        g_consts[4] = wmin; g_consts[5] = sw;
    }
}

// ============================================================================
// Launch 3: quantize BOTH matrices to f16 scratch (blockIdx.y: 0=x, 1=w).
// Bit-matches reference: IEEE rn div, clip, trunc-toward-zero.
// ============================================================================
__global__ void __launch_bounds__(256) quant_kernel(const float* __restrict__ x,
                                                    const float* __restrict__ w) {
    const int which = blockIdx.y;
    const float zero  = which ? g_consts[4] : g_consts[2];
    const float scale = which ? g_consts[5] : g_consts[3];
    const float* src = which ? w : x;
    unsigned short* dst = which ? g_wqh : g_xqh;
    const size_t i = ((size_t)blockIdx.x * 256 + threadIdx.x) * 8;
    const float4* s4 = reinterpret_cast<const float4*>(src + i);
    float4 a = s4[0], b = s4[1];
    float v[8] = {a.x, a.y, a.z, a.w, b.x, b.y, b.z, b.w};
    unsigned r[4];
    #pragma unroll
    for (int k = 0; k < 4; k++) {
        float q0 = fminf(fmaxf(__fdiv_rn(v[2 * k] - zero, scale) - 4.0f, -4.0f), 3.0f);
        float q1 = fminf(fmaxf(__fdiv_rn(v[2 * k + 1] - zero, scale) - 4.0f, -4.0f), 3.0f);
        unsigned lo = __half_as_ushort(__float2half_rn((float)(int)q0));
        unsigned hi = __half_as_ushort(__float2half_rn((float)(int)q1));
        r[k] = lo | (hi << 16);
    }
    *reinterpret_cast<uint4*>(dst + i) = make_uint4(r[0], r[1], r[2], r[3]);
}

// ============================================================================
// Launch 4 (ncu-captured slot): f16 HMMA GEMM, f32 accumulate.
// 128x128 tile, BK=64, 256 threads (2x4 warps, warp tile 64x32), 3-stage
// cp.async pipeline, ldmatrix.x4, fused dequant epilogue.
// D[m,n] = sum_k A[m,k]*B[n,k], both K-major f16.
// ============================================================================
__global__ void __launch_bounds__(256) gemm_kernel(const float* __restrict__ bias,
                                                   float* __restrict__ out) {
    extern __shared__ char smem[];
    const int tid = threadIdx.x, lane = tid & 31, wid = tid >> 5;
    const int warp_m = wid >> 2, warp_n = wid & 3;   // 2 x 4 warp grid
    const int bx = blockIdx.x, by = blockIdx.y;      // bx: N tiles, by: M tiles
    const uint32_t sm0 = smem_to_u32(smem);

    const unsigned short* Agbase = g_xqh + ((size_t)(by * BM) << 12);
    const unsigned short* Bgbase = g_wqh + ((size_t)(bx * BN) << 12);

    // copy-loop coords: 1024 16B-chunks per matrix per stage; 4 per thread
    int cp_so[4], cp_go[4];
    #pragma unroll
    for (int i = 0; i < 4; i++) {
        int id = tid + i * 256;
        int r = id >> 3, c = id & 7;
        cp_so[i] = r * 128 + ((c ^ (r & 7)) << 4);  // swizzled SMEM offset
        cp_go[i] = (r << 13) + (c << 4);            // gmem byte offset
    }

    const int a_row  = warp_m * 64 + (lane & 7) + ((lane >> 3) & 1) * 8;
    const int a_kbit = (lane >> 4) & 1;
    const int a_xor  = a_row & 7;
    uint32_t a_rowoff[4];
    #pragma unroll
    for (int mb = 0; mb < 4; mb++) a_rowoff[mb] = (uint32_t)(a_row + mb * 16) * 128;

    const int b_col  = warp_n * 32 + (lane & 7) + ((lane >> 3) & 1) * 8;
    const int b_kbit = (lane >> 4) & 1;
    const int b_xor  = b_col & 7;
    uint32_t b_rowoff[2];
    #pragma unroll
    for (int h = 0; h < 2; h++) b_rowoff[h] = (uint32_t)(b_col + h * 16) * 128;

    float acc[4][4][4];
    #pragma unroll
    for (int mb = 0; mb < 4; mb++)
        #pragma unroll
        for (int nb = 0; nb < 4; nb++)
            #pragma unroll
            for (int e = 0; e < 4; e++) acc[mb][nb][e] = 0.0f;

    auto load_stage = [&](int kt, int st) {
        const uint32_t As = sm0 + st * STAGE_BYTES;
        const uint32_t Bs = As + BM * 128;
        const unsigned short* Ag = Agbase + (size_t)kt * BK;
        const unsigned short* Bg = Bgbase + (size_t)kt * BK;
        #pragma unroll
        for (int i = 0; i < 4; i++) {
            CP_ASYNC16(As + cp_so[i], Ag + (cp_go[i] >> 1));
            CP_ASYNC16(Bs + cp_so[i], Bg + (cp_go[i] >> 1));
        }
    };

    load_stage(0, 0); CP_COMMIT();
    load_stage(1, 1); CP_COMMIT();

    int st = 0, nst = 2;
    #pragma unroll 1
    for (int kt = 0; kt < NITER; kt++) {
        CP_WAIT1();
        __syncthreads();
        if (kt + 2 < NITER) load_stage(kt + 2, nst);
        CP_COMMIT();

        const uint32_t As = sm0 + st * STAGE_BYTES;
        const uint32_t Bs = As + BM * 128;
        #pragma unroll
        for (int ks = 0; ks < 4; ks++) {  // 4 x k16 steps per BK=64
            const uint32_t ac = (uint32_t)(((2 * ks + a_kbit) ^ a_xor) << 4);
            const uint32_t bc = (uint32_t)(((2 * ks + b_kbit) ^ b_xor) << 4);
            uint32_t A[4][4], Bf[2][4];
            #pragma unroll
            for (int mb = 0; mb < 4; mb++) LDSM_X4(A[mb], As + a_rowoff[mb] + ac);
            #pragma unroll
            for (int h = 0; h < 2; h++)    LDSM_X4(Bf[h], Bs + b_rowoff[h] + bc);
            #pragma unroll
            for (int mb = 0; mb < 4; mb++) {
                MMA_F16(acc[mb][0], A[mb], Bf[0][0], Bf[0][2]);
                MMA_F16(acc[mb][1], A[mb], Bf[0][1], Bf[0][3]);
                MMA_F16(acc[mb][2], A[mb], Bf[1][0], Bf[1][2]);
                MMA_F16(acc[mb][3], A[mb], Bf[1][1], Bf[1][3]);
            }
        }
        st  = (st  == 2) ? 0 : st  + 1;
        nst = (nst == 2) ? 0 : nst + 1;
    }

    // Epilogue: out[r][c] = (acc + bias[c]) * s + shc * rowsum[r]
    const float s = g_consts[0], shc = g_consts[1];
    const int gr0 = by * BM + warp_m * 64 + (lane >> 2);
    const int gc0 = bx * BN + warp_n * 32 + (lane & 3) * 2;
    #pragma unroll
    for (int mb = 0; mb < 4; mb++) {
        const int r0 = gr0 + mb * 16, r1 = r0 + 8;
        const float sh0 = shc * g_rowsum[r0];
        const float sh1 = shc * g_rowsum[r1];
        float* o0 = out + ((size_t)r0 << 12);
        float* o1 = out + ((size_t)r1 << 12);
        #pragma unroll
        for (int nb = 0; nb < 4; nb++) {
            const int gc = gc0 + nb * 8;
            const float bv0 = bias[gc], bv1 = bias[gc + 1];
            float2 v0, v1;
            v0.x = fmaf(acc[mb][nb][0] + bv0, s, sh0);
            v0.y = fmaf(acc[mb][nb][1] + bv1, s, sh0);
            v1.x = fmaf(acc[mb][nb][2] + bv0, s, sh1);
            v1.y = fmaf(acc[mb][nb][3] + bv1, s, sh1);
            *reinterpret_cast<float2*>(o0 + gc) = v0;
            *reinterpret_cast<float2*>(o1 + gc) = v1;
        }
    }

    // Reset min/max accumulators for the next kernel_launch call (stream-
    // ordered before the next reduce_kernel).
    if (bx == 0 && by == 0 && tid == 0) {
        g_xmin_e = 0xFFFFFFFFu; g_xmax_e = 0u;
        g_wmin_e = 0xFFFFFFFFu; g_wmax_e = 0u;
    }
}

// ============================================================================
extern "C" void kernel_launch(void* const* d_in, const int* in_sizes, int n_in,
                              void* d_out, int out_size) {
    (void)in_sizes; (void)n_in; (void)out_size;
    const float* x    = (const float*)d_in[0];
    const float* w    = (const float*)d_in[1];
    const float* bias = (const float*)d_in[2];
    float* out = (float*)d_out;

    reduce_kernel<<<DIM, 256>>>(x, w);                            // launch 1
    finalize_kernel<<<1, 32>>>();                                 // launch 2
    quant_kernel<<<dim3(DIM * DIM / (8 * 256), 2), 256>>>(x, w);  // launch 3
    cudaFuncSetAttribute(gemm_kernel, cudaFuncAttributeMaxDynamicSharedMemorySize, SMEM_TOTAL);
    gemm_kernel<<<dim3(DIM / BN, DIM / BM), 256, SMEM_TOTAL>>>(bias, out);  // launch 4
}

// round 12
// speedup vs baseline: 1.1414x; 1.0151x over previous
#include <cuda_runtime.h>
#include <cuda_fp16.h>
#include <cstdint>
#include <cstddef>

// ============================================================================
// QUIK quantized linear, B = in = out = 4096.
//   x_q = trunc(clip((x - min(x))/((max-min)/8) - 4, -4, 3))   (global affine)
//   w_q likewise; out[i,j] = (x_q[i,:]·w_q[j,:] + bias[j])*s_a*s_w
//                            + (zero_a + 4*s_a)*rowsum_w[i]    (note index i)
// R11: persistent-CTA GEMM. R10 profile: tensor=64%, occ=2CTA/SM, grid 1024
// over 296 slots = 3.46 waves -> ~13.5% wave-tail idle. grid=296, tile loop.
// ============================================================================

#define DIM 4096
#define BM 128
#define BN 128
#define BK 64             // f16 elements per k-tile = 128 bytes per row
#define NITER (DIM / BK)  // 64
#define NTILES ((DIM / BM) * (DIM / BN))   // 1024
#define GRID_PERSIST 296                   // 2 CTAs x 148 SMs
#define STAGES 3
#define STAGE_BYTES (2 * BM * 128)         // A(16K) + B(16K) = 32768
#define SMEM_TOTAL (STAGES * STAGE_BYTES)  // 98304

// ---------------- device scratch (allocation-free rule) ---------------------
__device__ unsigned g_xmin_e = 0xFFFFFFFFu, g_xmax_e = 0u;
__device__ unsigned g_wmin_e = 0xFFFFFFFFu, g_wmax_e = 0u;
__device__ float g_rowsum[DIM];
__device__ float g_consts[8];  // 0:s=sa*sw 1:shiftc 2:x_zero 3:x_scale 4:w_zero 5:w_scale
__device__ unsigned short g_xqh[(size_t)DIM * DIM];  // f16 bits of quantized x
__device__ unsigned short g_wqh[(size_t)DIM * DIM];  // f16 bits of quantized w

// ---------------- PTX helpers (plain-sm80/75 features only) -----------------
__device__ __forceinline__ uint32_t smem_to_u32(const void* p) {
    uint32_t a;
    asm("{ .reg .u64 t; cvta.to.shared.u64 t, %1; cvt.u32.u64 %0, t; }" : "=r"(a) : "l"(p));
    return a;
}

#define CP_ASYNC16(saddr, gptr)                                              \
    asm volatile("cp.async.cg.shared.global [%0], [%1], 16;"                 \
                 :: "r"(saddr), "l"(gptr) : "memory")
#define CP_COMMIT() asm volatile("cp.async.commit_group;" ::: "memory")
#define CP_WAIT1()  asm volatile("cp.async.wait_group 1;" ::: "memory")
#define CP_WAIT0()  asm volatile("cp.async.wait_group 0;" ::: "memory")

#define LDSM_X4(r, addr)                                                     \
    asm volatile("ldmatrix.sync.aligned.m8n8.x4.shared.b16 {%0,%1,%2,%3}, [%4];" \
                 : "=r"((r)[0]), "=r"((r)[1]), "=r"((r)[2]), "=r"((r)[3])    \
                 : "r"(addr))

// f16 HMMA, f32 accumulate: D(16x8) += A(16x16) * B(16x8)
#define MMA_F16(c, a, b0v, b1v)                                              \
    asm volatile("mma.sync.aligned.m16n8k16.row.col.f32.f16.f16.f32 "        \
                 "{%0,%1,%2,%3}, {%4,%5,%6,%7}, {%8,%9}, {%0,%1,%2,%3};"     \
                 : "+f"((c)[0]), "+f"((c)[1]), "+f"((c)[2]), "+f"((c)[3])    \
                 : "r"((a)[0]), "r"((a)[1]), "r"((a)[2]), "r"((a)[3]),       \
                   "r"(b0v), "r"(b1v))

// Monotone float<->uint encoding for atomic min/max on fp32
__device__ __forceinline__ unsigned fenc(float f) {
    unsigned u = __float_as_uint(f);
    return (u & 0x80000000u) ? ~u : (u | 0x80000000u);
}
__device__ __forceinline__ float fdec(unsigned e) {
    return (e & 0x80000000u) ? __uint_as_float(e & 0x7FFFFFFFu) : __uint_as_float(~e);
}

// ============================================================================
// Launch 1: per-row pass — global min/max of x and w, weight row sums
// ============================================================================
__global__ void __launch_bounds__(256) reduce_kernel(const float* __restrict__ x,
                                                     const float* __restrict__ w) {
    const int row = blockIdx.x, tid = threadIdx.x;
    const float4* xr = reinterpret_cast<const float4*>(x + ((size_t)row << 12));
    const float4* wr = reinterpret_cast<const float4*>(w + ((size_t)row << 12));
    float xmn = 3.4e38f, xmx = -3.4e38f, wmn = 3.4e38f, wmx = -3.4e38f, ws = 0.0f;
    for (int i = tid; i < 1024; i += 256) {
        float4 a = xr[i];
        xmn = fminf(xmn, fminf(fminf(a.x, a.y), fminf(a.z, a.w)));
        xmx = fmaxf(xmx, fmaxf(fmaxf(a.x, a.y), fmaxf(a.z, a.w)));
        float4 b = wr[i];
        wmn = fminf(wmn, fminf(fminf(b.x, b.y), fminf(b.z, b.w)));
        wmx = fmaxf(wmx, fmaxf(fmaxf(b.x, b.y), fmaxf(b.z, b.w)));
        ws += (b.x + b.y) + (b.z + b.w);
    }
    #pragma unroll
    for (int o = 16; o; o >>= 1) {
        xmn = fminf(xmn, __shfl_xor_sync(0xFFFFFFFFu, xmn, o));
        xmx = fmaxf(xmx, __shfl_xor_sync(0xFFFFFFFFu, xmx, o));
        wmn = fminf(wmn, __shfl_xor_sync(0xFFFFFFFFu, wmn, o));
        wmx = fmaxf(wmx, __shfl_xor_sync(0xFFFFFFFFu, wmx, o));
        ws += __shfl_xor_sync(0xFFFFFFFFu, ws, o);
    }
    __shared__ float s_xmn[8], s_xmx[8], s_wmn[8], s_wmx[8], s_ws[8];
    const int wid = tid >> 5, lane = tid & 31;
    if (lane == 0) { s_xmn[wid] = xmn; s_xmx[wid] = xmx; s_wmn[wid] = wmn; s_wmx[wid] = wmx; s_ws[wid] = ws; }
    __syncthreads();
    if (tid == 0) {
        float a = s_xmn[0], b = s_xmx[0], c = s_wmn[0], d = s_wmx[0], e = s_ws[0];
        #pragma unroll
        for (int i = 1; i < 8; i++) {
            a = fminf(a, s_xmn[i]); b = fmaxf(b, s_xmx[i]);
            c = fminf(c, s_wmn[i]); d = fmaxf(d, s_wmx[i]);
            e += s_ws[i];
        }
        atomicMin(&g_xmin_e, fenc(a)); atomicMax(&g_xmax_e, fenc(b));
        atomicMin(&g_wmin_e, fenc(c)); atomicMax(&g_wmax_e, fenc(d));
        g_rowsum[row] = e;
    }
}

// ============================================================================
// Launch 2: scalar constants
// ============================================================================
__global__ void finalize_kernel() {
    if (threadIdx.x == 0) {
        float xmin = fdec(g_xmin_e), xmax = fdec(g_xmax_e);
        float wmin = fdec(g_wmin_e), wmax = fdec(g_wmax_e);
        float sa = (xmax - xmin) * 0.125f;  // /8 exact
        float sw = (wmax - wmin) * 0.125f;
        g_consts[0] = sa * sw;
        g_consts[1] = xmin + 4.0f * sa;
        g_consts[2] = xmin; g_consts[3] = sa;
        g_consts[4] = wmin; g_consts[5] = sw;
    }
}

// ============================================================================
// Launch 3: quantize BOTH matrices to f16 scratch (blockIdx.y: 0=x, 1=w).
// Bit-matches reference: IEEE rn div, clip, trunc-toward-zero.
// ============================================================================
__global__ void __launch_bounds__(256) quant_kernel(const float* __restrict__ x,
                                                    const float* __restrict__ w) {
    const int which = blockIdx.y;
    const float zero  = which ? g_consts[4] : g_consts[2];
    const float scale = which ? g_consts[5] : g_consts[3];
    const float* src = which ? w : x;
    unsigned short* dst = which ? g_wqh : g_xqh;
    const size_t i = ((size_t)blockIdx.x * 256 + threadIdx.x) * 8;
    const float4* s4 = reinterpret_cast<const float4*>(src + i);
    float4 a = s4[0], b = s4[1];
    float v[8] = {a.x, a.y, a.z, a.w, b.x, b.y, b.z, b.w};
    unsigned r[4];
    #pragma unroll
    for (int k = 0; k < 4; k++) {
        float q0 = fminf(fmaxf(__fdiv_rn(v[2 * k] - zero, scale) - 4.0f, -4.0f), 3.0f);
        float q1 = fminf(fmaxf(__fdiv_rn(v[2 * k + 1] - zero, scale) - 4.0f, -4.0f), 3.0f);
        unsigned lo = __half_as_ushort(__float2half_rn((float)(int)q0));
        unsigned hi = __half_as_ushort(__float2half_rn((float)(int)q1));
        r[k] = lo | (hi << 16);
    }
    *reinterpret_cast<uint4*>(dst + i) = make_uint4(r[0], r[1], r[2], r[3]);
}

// ============================================================================
// Launch 4 (ncu-captured slot): persistent f16 HMMA GEMM, f32 accumulate.
// grid=296 CTAs, each loops tiles with stride gridDim.x (no wave tail).
// Per tile: 128x128, BK=64, 3-stage cp.async pipeline, ldmatrix.x4, fused
// dequant epilogue. D[m,n] = sum_k A[m,k]*B[n,k], both K-major f16.
// ============================================================================
__global__ void __launch_bounds__(256, 2) gemm_kernel(const float* __restrict__ bias,
                                                      float* __restrict__ out) {
    extern __shared__ char smem[];
    const int tid = threadIdx.x, lane = tid & 31, wid = tid >> 5;
    const int warp_m = wid >> 2, warp_n = wid & 3;   // 2 x 4 warp grid
    const uint32_t sm0 = smem_to_u32(smem);

    // copy-loop coords: 1024 16B-chunks per matrix per stage; 4 per thread
    int cp_so[4], cp_go[4];
    #pragma unroll
    for (int i = 0; i < 4; i++) {
        int id = tid + i * 256;
        int r = id >> 3, c = id & 7;
        cp_so[i] = r * 128 + ((c ^ (r & 7)) << 4);  // swizzled SMEM offset
        cp_go[i] = (r << 13) + (c << 4);            // gmem byte offset
    }

    const int a_row  = warp_m * 64 + (lane & 7) + ((lane >> 3) & 1) * 8;
    const int a_kbit = (lane >> 4) & 1;
    const int a_xor  = a_row & 7;
    uint32_t a_rowoff[4];
    #pragma unroll
    for (int mb = 0; mb < 4; mb++) a_rowoff[mb] = (uint32_t)(a_row + mb * 16) * 128;

    const int b_col  = warp_n * 32 + (lane & 7) + ((lane >> 3) & 1) * 8;
    const int b_kbit = (lane >> 4) & 1;
    const int b_xor  = b_col & 7;
    uint32_t b_rowoff[2];
    #pragma unroll
    for (int h = 0; h < 2; h++) b_rowoff[h] = (uint32_t)(b_col + h * 16) * 128;

    const float s = g_consts[0], shc = g_consts[1];

    #pragma unroll 1
    for (int tile = blockIdx.x; tile < NTILES; tile += GRID_PERSIST) {
        const int by = tile >> 5, bx = tile & 31;   // 32 tiles per dim
        const unsigned short* Agbase = g_xqh + ((size_t)(by * BM) << 12);
        const unsigned short* Bgbase = g_wqh + ((size_t)(bx * BN) << 12);

        float acc[4][4][4];
        #pragma unroll
        for (int mb = 0; mb < 4; mb++)
            #pragma unroll
            for (int nb = 0; nb < 4; nb++)
                #pragma unroll
                for (int e = 0; e < 4; e++) acc[mb][nb][e] = 0.0f;

        auto load_stage = [&](int kt, int st) {
            const uint32_t As = sm0 + st * STAGE_BYTES;
            const uint32_t Bs = As + BM * 128;
            const unsigned short* Ag = Agbase + (size_t)kt * BK;
            const unsigned short* Bg = Bgbase + (size_t)kt * BK;
            #pragma unroll
            for (int i = 0; i < 4; i++) {
                CP_ASYNC16(As + cp_so[i], Ag + (cp_go[i] >> 1));
                CP_ASYNC16(Bs + cp_so[i], Bg + (cp_go[i] >> 1));
            }
        };

        load_stage(0, 0); CP_COMMIT();
        load_stage(1, 1); CP_COMMIT();

        int st = 0, nst = 2;
        #pragma unroll 1
        for (int kt = 0; kt < NITER; kt++) {
            CP_WAIT1();
            __syncthreads();
            if (kt + 2 < NITER) load_stage(kt + 2, nst);
            CP_COMMIT();

            const uint32_t As = sm0 + st * STAGE_BYTES;
            const uint32_t Bs = As + BM * 128;
            #pragma unroll
            for (int ks = 0; ks < 4; ks++) {  // 4 x k16 steps per BK=64
                const uint32_t ac = (uint32_t)(((2 * ks + a_kbit) ^ a_xor) << 4);
                const uint32_t bc = (uint32_t)(((2 * ks + b_kbit) ^ b_xor) << 4);
                uint32_t A[4][4], Bf[2][4];
                #pragma unroll
                for (int mb = 0; mb < 4; mb++) LDSM_X4(A[mb], As + a_rowoff[mb] + ac);
                #pragma unroll
                for (int h = 0; h < 2; h++)    LDSM_X4(Bf[h], Bs + b_rowoff[h] + bc);
                #pragma unroll
                for (int mb = 0; mb < 4; mb++) {
                    MMA_F16(acc[mb][0], A[mb], Bf[0][0], Bf[0][2]);
                    MMA_F16(acc[mb][1], A[mb], Bf[0][1], Bf[0][3]);
                    MMA_F16(acc[mb][2], A[mb], Bf[1][0], Bf[1][2]);
                    MMA_F16(acc[mb][3], A[mb], Bf[1][1], Bf[1][3]);
                }
            }
            st  = (st  == 2) ? 0 : st  + 1;
            nst = (nst == 2) ? 0 : nst + 1;
        }

        // drain remaining (empty) cp.async groups; keep smem safe for next tile
        CP_WAIT0();

        // Epilogue: out[r][c] = (acc + bias[c]) * s + shc * rowsum[r]
        const int gr0 = by * BM + warp_m * 64 + (lane >> 2);
        const int gc0 = bx * BN + warp_n * 32 + (lane & 3) * 2;
        #pragma unroll
        for (int mb = 0; mb < 4; mb++) {
            const int r0 = gr0 + mb * 16, r1 = r0 + 8;
            const float sh0 = shc * g_rowsum[r0];
            const float sh1 = shc * g_rowsum[r1];
            float* o0 = out + ((size_t)r0 << 12);
            float* o1 = out + ((size_t)r1 << 12);
            #pragma unroll
            for (int nb = 0; nb < 4; nb++) {
                const int gc = gc0 + nb * 8;
                const float bv0 = bias[gc], bv1 = bias[gc + 1];
                float2 v0, v1;
                v0.x = fmaf(acc[mb][nb][0] + bv0, s, sh0);
                v0.y = fmaf(acc[mb][nb][1] + bv1, s, sh0);
                v1.x = fmaf(acc[mb][nb][2] + bv0, s, sh1);
                v1.y = fmaf(acc[mb][nb][3] + bv1, s, sh1);
                *reinterpret_cast<float2*>(o0 + gc) = v0;
                *reinterpret_cast<float2*>(o1 + gc) = v1;
            }
        }
        __syncthreads();  // all warps done reading smem before next tile's loads
    }

    // Reset min/max accumulators for the next kernel_launch call (stream-
    // ordered before the next reduce_kernel).
    if (blockIdx.x == 0 && tid == 0) {
        g_xmin_e = 0xFFFFFFFFu; g_xmax_e = 0u;
        g_wmin_e = 0xFFFFFFFFu; g_wmax_e = 0u;
    }
}

// ============================================================================
extern "C" void kernel_launch(void* const* d_in, const int* in_sizes, int n_in,
                              void* d_out, int out_size) {
    (void)in_sizes; (void)n_in; (void)out_size;
    const float* x    = (const float*)d_in[0];
    const float* w    = (const float*)d_in[1];
    const float* bias = (const float*)d_in[2];
    float* out = (float*)d_out;

    reduce_kernel<<<DIM, 256>>>(x, w);                            // launch 1
    finalize_kernel<<<1, 32>>>();                                 // launch 2
    quant_kernel<<<dim3(DIM * DIM / (8 * 256), 2), 256>>>(x, w);  // launch 3
    cudaFuncSetAttribute(gemm_kernel, cudaFuncAttributeMaxDynamicSharedMemorySize, SMEM_TOTAL);
    gemm_kernel<<<GRID_PERSIST, 256, SMEM_TOTAL>>>(bias, out);    // launch 4
}

// round 13
// speedup vs baseline: 1.1474x; 1.0053x over previous
#include <cuda_runtime.h>
#include <cuda_fp16.h>
#include <cstdint>
#include <cstddef>

// ============================================================================
// QUIK quantized linear, B = in = out = 4096.
//   x_q = trunc(clip((x - min(x))/((max-min)/8) - 4, -4, 3))   (global affine)
//   w_q likewise; out[i,j] = (x_q[i,:]·w_q[j,:] + bias[j])*s_a*s_w
//                            + (zero_a + 4*s_a)*rowsum_w[i]    (note index i)
// R13: R12 profile showed smem crossbar co-limiting (L1=53% @ tensor=65%;
// model: 96KB smem reads per kt per CTA = 75% of crossbar at full tensor).
// Switch to 4 warps/CTA, warp tile 64x64: 64KB per kt per CTA (50% headroom),
// LDSM:MMA 8:32 instead of 6:16, ALU/MMA halved. Still 2 CTAs/SM, 8 warps/SM.
// ============================================================================

#define DIM 4096
#define BM 128
#define BN 128
#define BK 64             // f16 elements per k-tile = 128 bytes per row
#define NITER (DIM / BK)  // 64
#define NTILES ((DIM / BM) * (DIM / BN))   // 1024
#define GRID_PERSIST 296                   // 2 CTAs x 148 SMs
#define STAGES 3
#define STAGE_BYTES (2 * BM * 128)         // A(16K) + B(16K) = 32768
#define SMEM_TOTAL (STAGES * STAGE_BYTES)  // 98304

// ---------------- device scratch (allocation-free rule) ---------------------
__device__ unsigned g_xmin_e = 0xFFFFFFFFu, g_xmax_e = 0u;
__device__ unsigned g_wmin_e = 0xFFFFFFFFu, g_wmax_e = 0u;
__device__ float g_rowsum[DIM];
__device__ float g_consts[8];  // 0:s=sa*sw 1:shiftc 2:x_zero 3:x_scale 4:w_zero 5:w_scale
__device__ unsigned short g_xqh[(size_t)DIM * DIM];  // f16 bits of quantized x
__device__ unsigned short g_wqh[(size_t)DIM * DIM];  // f16 bits of quantized w

// ---------------- PTX helpers (plain-sm80/75 features only) -----------------
__device__ __forceinline__ uint32_t smem_to_u32(const void* p) {
    uint32_t a;
    asm("{ .reg .u64 t; cvta.to.shared.u64 t, %1; cvt.u32.u64 %0, t; }" : "=r"(a) : "l"(p));
    return a;
}

#define CP_ASYNC16(saddr, gptr)                                              \
    asm volatile("cp.async.cg.shared.global [%0], [%1], 16;"                 \
                 :: "r"(saddr), "l"(gptr) : "memory")
#define CP_COMMIT() asm volatile("cp.async.commit_group;" ::: "memory")
#define CP_WAIT1()  asm volatile("cp.async.wait_group 1;" ::: "memory")
#define CP_WAIT0()  asm volatile("cp.async.wait_group 0;" ::: "memory")

#define LDSM_X4(r, addr)                                                     \
    asm volatile("ldmatrix.sync.aligned.m8n8.x4.shared.b16 {%0,%1,%2,%3}, [%4];" \
                 : "=r"((r)[0]), "=r"((r)[1]), "=r"((r)[2]), "=r"((r)[3])    \
                 : "r"(addr))

// f16 HMMA, f32 accumulate: D(16x8) += A(16x16) * B(16x8)
#define MMA_F16(c, a, b0v, b1v)                                              \
    asm volatile("mma.sync.aligned.m16n8k16.row.col.f32.f16.f16.f32 "        \
                 "{%0,%1,%2,%3}, {%4,%5,%6,%7}, {%8,%9}, {%0,%1,%2,%3};"     \
                 : "+f"((c)[0]), "+f"((c)[1]), "+f"((c)[2]), "+f"((c)[3])    \
                 : "r"((a)[0]), "r"((a)[1]), "r"((a)[2]), "r"((a)[3]),       \
                   "r"(b0v), "r"(b1v))

// Monotone float<->uint encoding for atomic min/max on fp32
__device__ __forceinline__ unsigned fenc(float f) {
    unsigned u = __float_as_uint(f);
    return (u & 0x80000000u) ? ~u : (u | 0x80000000u);
}
__device__ __forceinline__ float fdec(unsigned e) {
    return (e & 0x80000000u) ? __uint_as_float(e & 0x7FFFFFFFu) : __uint_as_float(~e);
}

// ============================================================================
// Launch 1: per-row pass — global min/max of x and w, weight row sums
// ============================================================================
__global__ void __launch_bounds__(256) reduce_kernel(const float* __restrict__ x,
                                                     const float* __restrict__ w) {
    const int row = blockIdx.x, tid = threadIdx.x;
    const float4* xr = reinterpret_cast<const float4*>(x + ((size_t)row << 12));
    const float4* wr = reinterpret_cast<const float4*>(w + ((size_t)row << 12));
    float xmn = 3.4e38f, xmx = -3.4e38f, wmn = 3.4e38f, wmx = -3.4e38f, ws = 0.0f;
    for (int i = tid; i < 1024; i += 256) {
        float4 a = xr[i];
        xmn = fminf(xmn, fminf(fminf(a.x, a.y), fminf(a.z, a.w)));
        xmx = fmaxf(xmx, fmaxf(fmaxf(a.x, a.y), fmaxf(a.z, a.w)));
        float4 b = wr[i];
        wmn = fminf(wmn, fminf(fminf(b.x, b.y), fminf(b.z, b.w)));
        wmx = fmaxf(wmx, fmaxf(fmaxf(b.x, b.y), fmaxf(b.z, b.w)));
        ws += (b.x + b.y) + (b.z + b.w);
    }
    #pragma unroll
    for (int o = 16; o; o >>= 1) {
        xmn = fminf(xmn, __shfl_xor_sync(0xFFFFFFFFu, xmn, o));
        xmx = fmaxf(xmx, __shfl_xor_sync(0xFFFFFFFFu, xmx, o));
        wmn = fminf(wmn, __shfl_xor_sync(0xFFFFFFFFu, wmn, o));
        wmx = fmaxf(wmx, __shfl_xor_sync(0xFFFFFFFFu, wmx, o));
        ws += __shfl_xor_sync(0xFFFFFFFFu, ws, o);
    }
    __shared__ float s_xmn[8], s_xmx[8], s_wmn[8], s_wmx[8], s_ws[8];
    const int wid = tid >> 5, lane = tid & 31;
    if (lane == 0) { s_xmn[wid] = xmn; s_xmx[wid] = xmx; s_wmn[wid] = wmn; s_wmx[wid] = wmx; s_ws[wid] = ws; }
    __syncthreads();
    if (tid == 0) {
        float a = s_xmn[0], b = s_xmx[0], c = s_wmn[0], d = s_wmx[0], e = s_ws[0];
        #pragma unroll
        for (int i = 1; i < 8; i++) {
            a = fminf(a, s_xmn[i]); b = fmaxf(b, s_xmx[i]);
            c = fminf(c, s_wmn[i]); d = fmaxf(d, s_wmx[i]);
            e += s_ws[i];
        }
        atomicMin(&g_xmin_e, fenc(a)); atomicMax(&g_xmax_e, fenc(b));
        atomicMin(&g_wmin_e, fenc(c)); atomicMax(&g_wmax_e, fenc(d));
        g_rowsum[row] = e;
    }
}

// ============================================================================
// Launch 2: scalar constants
// ============================================================================
__global__ void finalize_kernel() {
    if (threadIdx.x == 0) {
        float xmin = fdec(g_xmin_e), xmax = fdec(g_xmax_e);
        float wmin = fdec(g_wmin_e), wmax = fdec(g_wmax_e);
        float sa = (xmax - xmin) * 0.125f;  // /8 exact
        float sw = (wmax - wmin) * 0.125f;
        g_consts[0] = sa * sw;
        g_consts[1] = xmin + 4.0f * sa;
        g_consts[2] = xmin; g_consts[3] = sa;
        g_consts[4] = wmin; g_consts[5] = sw;
    }
}

// ============================================================================
// Launch 3: quantize BOTH matrices to f16 scratch (blockIdx.y: 0=x, 1=w).
// Bit-matches reference: IEEE rn div, clip, trunc-toward-zero.
// ============================================================================
__global__ void __launch_bounds__(256) quant_kernel(const float* __restrict__ x,
                                                    const float* __restrict__ w) {
    const int which = blockIdx.y;
    const float zero  = which ? g_consts[4] : g_consts[2];
    const float scale = which ? g_consts[5] : g_consts[3];
    const float* src = which ? w : x;
    unsigned short* dst = which ? g_wqh : g_xqh;
    const size_t i = ((size_t)blockIdx.x * 256 + threadIdx.x) * 8;
    const float4* s4 = reinterpret_cast<const float4*>(src + i);
    float4 a = s4[0], b = s4[1];
    float v[8] = {a.x, a.y, a.z, a.w, b.x, b.y, b.z, b.w};
    unsigned r[4];
    #pragma unroll
    for (int k = 0; k < 4; k++) {
        float q0 = fminf(fmaxf(__fdiv_rn(v[2 * k] - zero, scale) - 4.0f, -4.0f), 3.0f);
        float q1 = fminf(fmaxf(__fdiv_rn(v[2 * k + 1] - zero, scale) - 4.0f, -4.0f), 3.0f);
        unsigned lo = __half_as_ushort(__float2half_rn((float)(int)q0));
        unsigned hi = __half_as_ushort(__float2half_rn((float)(int)q1));
        r[k] = lo | (hi << 16);
    }
    *reinterpret_cast<uint4*>(dst + i) = make_uint4(r[0], r[1], r[2], r[3]);
}

// ============================================================================
// Launch 4 (ncu-captured slot): persistent f16 HMMA GEMM, f32 accumulate.
// 128 threads = 4 warps (2x2), warp tile 64x64; block tile 128x128; BK=64;
// 3-stage cp.async pipeline; ldmatrix.x4; fused dequant epilogue.
// ============================================================================
__global__ void __launch_bounds__(128, 2) gemm_kernel(const float* __restrict__ bias,
                                                      float* __restrict__ out) {
    extern __shared__ char smem[];
    const int tid = threadIdx.x, lane = tid & 31, wid = tid >> 5;
    const int warp_m = wid >> 1, warp_n = wid & 1;   // 2 x 2 warp grid
    const uint32_t sm0 = smem_to_u32(smem);

    // copy-loop: 2048 16B-chunks per stage (A 1024 + B 1024); 16 per thread.
    // Row index for chunk i: rc + i*16 (i*16 ≡ 0 mod 8 -> constant swizzle xor)
    const int cp_rc = tid >> 3;            // 0..15
    const int cp_c  = tid & 7;
    const uint32_t cp_sbase = (uint32_t)(cp_rc * 128 + ((cp_c ^ (cp_rc & 7)) << 4));
    const uint32_t cp_gbase = ((uint32_t)cp_rc << 13) + ((uint32_t)cp_c << 4);

    const int a_row  = warp_m * 64 + (lane & 7) + ((lane >> 3) & 1) * 8;
    const int a_kbit = (lane >> 4) & 1;
    const int a_xor  = a_row & 7;
    uint32_t a_rowoff[4];
    #pragma unroll
    for (int mb = 0; mb < 4; mb++) a_rowoff[mb] = (uint32_t)(a_row + mb * 16) * 128;

    const int b_col  = warp_n * 64 + (lane & 7) + ((lane >> 3) & 1) * 8;
    const int b_kbit = (lane >> 4) & 1;
    const int b_xor  = b_col & 7;
    uint32_t b_rowoff[4];
    #pragma unroll
    for (int h = 0; h < 4; h++) b_rowoff[h] = (uint32_t)(b_col + h * 16) * 128;

    const float s = g_consts[0], shc = g_consts[1];

    #pragma unroll 1
    for (int tile = blockIdx.x; tile < NTILES; tile += GRID_PERSIST) {
        const int by = tile >> 5, bx = tile & 31;   // 32 tiles per dim
        const unsigned short* Agbase = g_xqh + ((size_t)(by * BM) << 12);
        const unsigned short* Bgbase = g_wqh + ((size_t)(bx * BN) << 12);

        float acc[4][8][4];  // 128 regs: warp tile 64x64
        #pragma unroll
        for (int mb = 0; mb < 4; mb++)
            #pragma unroll
            for (int nb = 0; nb < 8; nb++)
                #pragma unroll
                for (int e = 0; e < 4; e++) acc[mb][nb][e] = 0.0f;

        auto load_stage = [&](int kt, int st) {
            const uint32_t As = sm0 + st * STAGE_BYTES;
            const uint32_t Bs = As + BM * 128;
            const char* Ag = reinterpret_cast<const char*>(Agbase + (size_t)kt * BK) + cp_gbase;
            const char* Bg = reinterpret_cast<const char*>(Bgbase + (size_t)kt * BK) + cp_gbase;
            #pragma unroll
            for (int i = 0; i < 8; i++) {  // rows cp_rc + i*16 cover 0..127
                CP_ASYNC16(As + cp_sbase + i * 2048, Ag + i * (size_t)131072);
                CP_ASYNC16(Bs + cp_sbase + i * 2048, Bg + i * (size_t)131072);
            }
        };

        load_stage(0, 0); CP_COMMIT();
        load_stage(1, 1); CP_COMMIT();

        int st = 0, nst = 2;
        #pragma unroll 1
        for (int kt = 0; kt < NITER; kt++) {
            CP_WAIT1();
            __syncthreads();
            if (kt + 2 < NITER) load_stage(kt + 2, nst);
            CP_COMMIT();

            const uint32_t As = sm0 + st * STAGE_BYTES;
            const uint32_t Bs = As + BM * 128;
            #pragma unroll
            for (int ks = 0; ks < 4; ks++) {  // 4 x k16 steps per BK=64
                const uint32_t ac = (uint32_t)(((2 * ks + a_kbit) ^ a_xor) << 4);
                const uint32_t bc = (uint32_t)(((2 * ks + b_kbit) ^ b_xor) << 4);
                uint32_t A[4][4], Bf[4][4];
                #pragma unroll
                for (int mb = 0; mb < 4; mb++) LDSM_X4(A[mb], As + a_rowoff[mb] + ac);
                #pragma unroll
                for (int h = 0; h < 4; h++)    LDSM_X4(Bf[h], Bs + b_rowoff[h] + bc);
                // Bf[h]: m0=(n0-7,klo) m1=(n8-15,klo) m2=(n0-7,khi) m3=(n8-15,khi)
                #pragma unroll
                for (int mb = 0; mb < 4; mb++)
                    #pragma unroll
                    for (int h = 0; h < 4; h++) {
                        MMA_F16(acc[mb][2 * h],     A[mb], Bf[h][0], Bf[h][2]);
                        MMA_F16(acc[mb][2 * h + 1], A[mb], Bf[h][1], Bf[h][3]);
                    }
            }
            st  = (st  == 2) ? 0 : st  + 1;
            nst = (nst == 2) ? 0 : nst + 1;
        }

        CP_WAIT0();  // drain before smem reuse in next tile

        // Epilogue: out[r][c] = (acc + bias[c]) * s + shc * rowsum[r]
        const int gr0 = by * BM + warp_m * 64 + (lane >> 2);
        const int gc0 = bx * BN + warp_n * 64 + (lane & 3) * 2;
        #pragma unroll
        for (int mb = 0; mb < 4; mb++) {
            const int r0 = gr0 + mb * 16, r1 = r0 + 8;
            const float sh0 = shc * g_rowsum[r0];
            const float sh1 = shc * g_rowsum[r1];
            float* o0 = out + ((size_t)r0 << 12);
            float* o1 = out + ((size_t)r1 << 12);
            #pragma unroll
            for (int nb = 0; nb < 8; nb++) {
                const int gc = gc0 + nb * 8;
                const float bv0 = bias[gc], bv1 = bias[gc + 1];
                float2 v0, v1;
                v0.x = fmaf(acc[mb][nb][0] + bv0, s, sh0);
                v0.y = fmaf(acc[mb][nb][1] + bv1, s, sh0);
                v1.x = fmaf(acc[mb][nb][2] + bv0, s, sh1);
                v1.y = fmaf(acc[mb][nb][3] + bv1, s, sh1);
                *reinterpret_cast<float2*>(o0 + gc) = v0;
                *reinterpret_cast<float2*>(o1 + gc) = v1;
            }
        }
        __syncthreads();  // all warps done reading smem before next tile's loads
    }

    // Reset min/max accumulators for the next kernel_launch call
    if (blockIdx.x == 0 && tid == 0) {
        g_xmin_e = 0xFFFFFFFFu; g_xmax_e = 0u;
        g_wmin_e = 0xFFFFFFFFu; g_wmax_e = 0u;
    }
}

// ============================================================================
extern "C" void kernel_launch(void* const* d_in, const int* in_sizes, int n_in,
                              void* d_out, int out_size) {
    (void)in_sizes; (void)n_in; (void)out_size;
    const float* x    = (const float*)d_in[0];
    const float* w    = (const float*)d_in[1];
    const float* bias = (const float*)d_in[2];
    float* out = (float*)d_out;

    reduce_kernel<<<DIM, 256>>>(x, w);                            // launch 1
    finalize_kernel<<<1, 32>>>();                                 // launch 2
    quant_kernel<<<dim3(DIM * DIM / (8 * 256), 2), 256>>>(x, w);  // launch 3
    cudaFuncSetAttribute(gemm_kernel, cudaFuncAttributeMaxDynamicSharedMemorySize, SMEM_TOTAL);
    gemm_kernel<<<GRID_PERSIST, 128, SMEM_TOTAL>>>(bias, out);    // launch 4
}

// round 14
// speedup vs baseline: 1.2958x; 1.1293x over previous
#include <cuda_runtime.h>
#include <cuda_fp16.h>
#include <cstdint>
#include <cstddef>

// ============================================================================
// QUIK quantized linear, B = in = out = 4096.
//   x_q = trunc(clip((x - min(x))/((max-min)/8) - 4, -4, 3))   (global affine)
//   w_q likewise; out[i,j] = (x_q[i,:]·w_q[j,:] + bias[j])*s_a*s_w
//                            + (zero_a + 4*s_a)*rowsum_w[i]    (note index i)
// R14: fragment double-buffering. R13 proved tensor pinned at 65% regardless
// of smem traffic -> LDSM->MMA RAW bubbles (barrier phase-locks both warps
// into simultaneous LDSM bursts). Prefetch ks+1 fragments (and next-stage
// ks=0 across the kt boundary) before the ks MMA block: MMA issue continuous.
// ============================================================================

#define DIM 4096
#define BM 128
#define BN 128
#define BK 64             // f16 elements per k-tile = 128 bytes per row
#define NITER (DIM / BK)  // 64
#define NTILES ((DIM / BM) * (DIM / BN))   // 1024
#define GRID_PERSIST 296                   // 2 CTAs x 148 SMs
#define STAGES 3
#define STAGE_BYTES (2 * BM * 128)         // A(16K) + B(16K) = 32768
#define SMEM_TOTAL (STAGES * STAGE_BYTES)  // 98304

// ---------------- device scratch (allocation-free rule) ---------------------
__device__ unsigned g_xmin_e = 0xFFFFFFFFu, g_xmax_e = 0u;
__device__ unsigned g_wmin_e = 0xFFFFFFFFu, g_wmax_e = 0u;
__device__ float g_rowsum[DIM];
__device__ float g_consts[8];  // 0:s=sa*sw 1:shiftc 2:x_zero 3:x_scale 4:w_zero 5:w_scale
__device__ unsigned short g_xqh[(size_t)DIM * DIM];  // f16 bits of quantized x
__device__ unsigned short g_wqh[(size_t)DIM * DIM];  // f16 bits of quantized w

// ---------------- PTX helpers (plain-sm80/75 features only) -----------------
__device__ __forceinline__ uint32_t smem_to_u32(const void* p) {
    uint32_t a;
    asm("{ .reg .u64 t; cvta.to.shared.u64 t, %1; cvt.u32.u64 %0, t; }" : "=r"(a) : "l"(p));
    return a;
}

#define CP_ASYNC16(saddr, gptr)                                              \
    asm volatile("cp.async.cg.shared.global [%0], [%1], 16;"                 \
                 :: "r"(saddr), "l"(gptr) : "memory")
#define CP_COMMIT() asm volatile("cp.async.commit_group;" ::: "memory")
#define CP_WAIT1()  asm volatile("cp.async.wait_group 1;" ::: "memory")
#define CP_WAIT0()  asm volatile("cp.async.wait_group 0;" ::: "memory")

#define LDSM_X4(r, addr)                                                     \
    asm volatile("ldmatrix.sync.aligned.m8n8.x4.shared.b16 {%0,%1,%2,%3}, [%4];" \
                 : "=r"((r)[0]), "=r"((r)[1]), "=r"((r)[2]), "=r"((r)[3])    \
                 : "r"(addr))

// f16 HMMA, f32 accumulate: D(16x8) += A(16x16) * B(16x8)
#define MMA_F16(c, a, b0v, b1v)                                              \
    asm volatile("mma.sync.aligned.m16n8k16.row.col.f32.f16.f16.f32 "        \
                 "{%0,%1,%2,%3}, {%4,%5,%6,%7}, {%8,%9}, {%0,%1,%2,%3};"     \
                 : "+f"((c)[0]), "+f"((c)[1]), "+f"((c)[2]), "+f"((c)[3])    \
                 : "r"((a)[0]), "r"((a)[1]), "r"((a)[2]), "r"((a)[3]),       \
                   "r"(b0v), "r"(b1v))

// Monotone float<->uint encoding for atomic min/max on fp32
__device__ __forceinline__ unsigned fenc(float f) {
    unsigned u = __float_as_uint(f);
    return (u & 0x80000000u) ? ~u : (u | 0x80000000u);
}
__device__ __forceinline__ float fdec(unsigned e) {
    return (e & 0x80000000u) ? __uint_as_float(e & 0x7FFFFFFFu) : __uint_as_float(~e);
}

// ============================================================================
// Launch 1: per-row pass — global min/max of x and w, weight row sums
// ============================================================================
__global__ void __launch_bounds__(256) reduce_kernel(const float* __restrict__ x,
                                                     const float* __restrict__ w) {
    const int row = blockIdx.x, tid = threadIdx.x;
    const float4* xr = reinterpret_cast<const float4*>(x + ((size_t)row << 12));
    const float4* wr = reinterpret_cast<const float4*>(w + ((size_t)row << 12));
    float xmn = 3.4e38f, xmx = -3.4e38f, wmn = 3.4e38f, wmx = -3.4e38f, ws = 0.0f;
    for (int i = tid; i < 1024; i += 256) {
        float4 a = xr[i];
        xmn = fminf(xmn, fminf(fminf(a.x, a.y), fminf(a.z, a.w)));
        xmx = fmaxf(xmx, fmaxf(fmaxf(a.x, a.y), fmaxf(a.z, a.w)));
        float4 b = wr[i];
        wmn = fminf(wmn, fminf(fminf(b.x, b.y), fminf(b.z, b.w)));
        wmx = fmaxf(wmx, fmaxf(fmaxf(b.x, b.y), fmaxf(b.z, b.w)));
        ws += (b.x + b.y) + (b.z + b.w);
    }
    #pragma unroll
    for (int o = 16; o; o >>= 1) {
        xmn = fminf(xmn, __shfl_xor_sync(0xFFFFFFFFu, xmn, o));
        xmx = fmaxf(xmx, __shfl_xor_sync(0xFFFFFFFFu, xmx, o));
        wmn = fminf(wmn, __shfl_xor_sync(0xFFFFFFFFu, wmn, o));
        wmx = fmaxf(wmx, __shfl_xor_sync(0xFFFFFFFFu, wmx, o));
        ws += __shfl_xor_sync(0xFFFFFFFFu, ws, o);
    }
    __shared__ float s_xmn[8], s_xmx[8], s_wmn[8], s_wmx[8], s_ws[8];
    const int wid = tid >> 5, lane = tid & 31;
    if (lane == 0) { s_xmn[wid] = xmn; s_xmx[wid] = xmx; s_wmn[wid] = wmn; s_wmx[wid] = wmx; s_ws[wid] = ws; }
    __syncthreads();
    if (tid == 0) {
        float a = s_xmn[0], b = s_xmx[0], c = s_wmn[0], d = s_wmx[0], e = s_ws[0];
        #pragma unroll
        for (int i = 1; i < 8; i++) {
            a = fminf(a, s_xmn[i]); b = fmaxf(b, s_xmx[i]);
            c = fminf(c, s_wmn[i]); d = fmaxf(d, s_wmx[i]);
            e += s_ws[i];
        }
        atomicMin(&g_xmin_e, fenc(a)); atomicMax(&g_xmax_e, fenc(b));
        atomicMin(&g_wmin_e, fenc(c)); atomicMax(&g_wmax_e, fenc(d));
        g_rowsum[row] = e;
    }
}

// ============================================================================
// Launch 2: scalar constants
// ============================================================================
__global__ void finalize_kernel() {
    if (threadIdx.x == 0) {
        float xmin = fdec(g_xmin_e), xmax = fdec(g_xmax_e);
        float wmin = fdec(g_wmin_e), wmax = fdec(g_wmax_e);
        float sa = (xmax - xmin) * 0.125f;  // /8 exact
        float sw = (wmax - wmin) * 0.125f;
        g_consts[0] = sa * sw;
        g_consts[1] = xmin + 4.0f * sa;
        g_consts[2] = xmin; g_consts[3] = sa;
        g_consts[4] = wmin; g_consts[5] = sw;
    }
}

// ============================================================================
// Launch 3: quantize BOTH matrices to f16 scratch (blockIdx.y: 0=x, 1=w).
// ============================================================================
__global__ void __launch_bounds__(256) quant_kernel(const float* __restrict__ x,
                                                    const float* __restrict__ w) {
    const int which = blockIdx.y;
    const float zero  = which ? g_consts[4] : g_consts[2];
    const float scale = which ? g_consts[5] : g_consts[3];
    const float* src = which ? w : x;
    unsigned short* dst = which ? g_wqh : g_xqh;
    const size_t i = ((size_t)blockIdx.x * 256 + threadIdx.x) * 8;
    const float4* s4 = reinterpret_cast<const float4*>(src + i);
    float4 a = s4[0], b = s4[1];
    float v[8] = {a.x, a.y, a.z, a.w, b.x, b.y, b.z, b.w};
    unsigned r[4];
    #pragma unroll
    for (int k = 0; k < 4; k++) {
        float q0 = fminf(fmaxf(__fdiv_rn(v[2 * k] - zero, scale) - 4.0f, -4.0f), 3.0f);
        float q1 = fminf(fmaxf(__fdiv_rn(v[2 * k + 1] - zero, scale) - 4.0f, -4.0f), 3.0f);
        unsigned lo = __half_as_ushort(__float2half_rn((float)(int)q0));
        unsigned hi = __half_as_ushort(__float2half_rn((float)(int)q1));
        r[k] = lo | (hi << 16);
    }
    *reinterpret_cast<uint4*>(dst + i) = make_uint4(r[0], r[1], r[2], r[3]);
}

// ============================================================================
// Launch 4 (ncu-captured slot): persistent f16 HMMA GEMM, f32 accumulate,
// register fragment double-buffering. 128 threads = 4 warps (2x2), warp tile
// 64x64; block tile 128x128; BK=64; 3-stage cp.async pipeline.
// ============================================================================
__global__ void __launch_bounds__(128, 2) gemm_kernel(const float* __restrict__ bias,
                                                      float* __restrict__ out) {
    extern __shared__ char smem[];
    const int tid = threadIdx.x, lane = tid & 31, wid = tid >> 5;
    const int warp_m = wid >> 1, warp_n = wid & 1;   // 2 x 2 warp grid
    const uint32_t sm0 = smem_to_u32(smem);

    // copy-loop: 2048 16B-chunks per stage; 16 per thread
    const int cp_rc = tid >> 3;            // 0..15
    const int cp_c  = tid & 7;
    const uint32_t cp_sbase = (uint32_t)(cp_rc * 128 + ((cp_c ^ (cp_rc & 7)) << 4));
    const uint32_t cp_gbase = ((uint32_t)cp_rc << 13) + ((uint32_t)cp_c << 4);

    const int a_row  = warp_m * 64 + (lane & 7) + ((lane >> 3) & 1) * 8;
    const int a_kbit = (lane >> 4) & 1;
    const int a_xor  = a_row & 7;
    uint32_t a_rowoff[4];
    #pragma unroll
    for (int mb = 0; mb < 4; mb++) a_rowoff[mb] = (uint32_t)(a_row + mb * 16) * 128;

    const int b_col  = warp_n * 64 + (lane & 7) + ((lane >> 3) & 1) * 8;
    const int b_kbit = (lane >> 4) & 1;
    const int b_xor  = b_col & 7;
    uint32_t b_rowoff[4];
    #pragma unroll
    for (int h = 0; h < 4; h++) b_rowoff[h] = (uint32_t)(b_col + h * 16) * 128;

    // per-ks swizzled column offsets (precomputed: kills per-ks ALU)
    uint32_t ac_k[4], bc_k[4];
    #pragma unroll
    for (int ks = 0; ks < 4; ks++) {
        ac_k[ks] = (uint32_t)(((2 * ks + a_kbit) ^ a_xor) << 4);
        bc_k[ks] = (uint32_t)(((2 * ks + b_kbit) ^ b_xor) << 4);
    }

    const float s = g_consts[0], shc = g_consts[1];

    uint32_t Af[2][4][4], Bff[2][4][4];  // double-buffered fragments

    #pragma unroll 1
    for (int tile = blockIdx.x; tile < NTILES; tile += GRID_PERSIST) {
        const int by = tile >> 5, bx = tile & 31;
        const unsigned short* Agbase = g_xqh + ((size_t)(by * BM) << 12);
        const unsigned short* Bgbase = g_wqh + ((size_t)(bx * BN) << 12);

        float acc[4][8][4];
        #pragma unroll
        for (int mb = 0; mb < 4; mb++)
            #pragma unroll
            for (int nb = 0; nb < 8; nb++)
                #pragma unroll
                for (int e = 0; e < 4; e++) acc[mb][nb][e] = 0.0f;

        auto load_stage = [&](int kt, int st) {
            const uint32_t As = sm0 + st * STAGE_BYTES;
            const uint32_t Bs = As + BM * 128;
            const char* Ag = reinterpret_cast<const char*>(Agbase + (size_t)kt * BK) + cp_gbase;
            const char* Bg = reinterpret_cast<const char*>(Bgbase + (size_t)kt * BK) + cp_gbase;
            #pragma unroll
            for (int i = 0; i < 8; i++) {
                CP_ASYNC16(As + cp_sbase + i * 2048, Ag + i * (size_t)131072);
                CP_ASYNC16(Bs + cp_sbase + i * 2048, Bg + i * (size_t)131072);
            }
        };
        auto ldsm_frags = [&](int buf, uint32_t As, int ks) {
            const uint32_t Bs = As + BM * 128;
            #pragma unroll
            for (int mb = 0; mb < 4; mb++) LDSM_X4(Af[buf][mb],  As + a_rowoff[mb] + ac_k[ks]);
            #pragma unroll
            for (int h = 0; h < 4; h++)    LDSM_X4(Bff[buf][h],  Bs + b_rowoff[h] + bc_k[ks]);
        };
        auto mma_block = [&](int buf) {
            #pragma unroll
            for (int mb = 0; mb < 4; mb++)
                #pragma unroll
                for (int h = 0; h < 4; h++) {
                    MMA_F16(acc[mb][2 * h],     Af[buf][mb], Bff[buf][h][0], Bff[buf][h][2]);
                    MMA_F16(acc[mb][2 * h + 1], Af[buf][mb], Bff[buf][h][1], Bff[buf][h][3]);
                }
        };

        load_stage(0, 0); CP_COMMIT();
        load_stage(1, 1); CP_COMMIT();
        CP_WAIT1();
        __syncthreads();
        ldsm_frags(0, sm0, 0);  // stage 0, ks 0 -> buf 0

        int st = 0, nst = 2;
        #pragma unroll 1
        for (int kt = 0; kt < NITER; kt++) {
            const uint32_t As = sm0 + st * STAGE_BYTES;
            if (kt + 2 < NITER) { load_stage(kt + 2, nst); }
            CP_COMMIT();

            #pragma unroll
            for (int ks = 0; ks < 3; ks++) {
                ldsm_frags((ks + 1) & 1, As, ks + 1);  // prefetch next ks
                mma_block(ks & 1);
            }
            if (kt + 1 < NITER) {
                CP_WAIT1();          // next stage resident
                __syncthreads();     // all CTA threads see it; stage kt-1 free
                const uint32_t Asn = sm0 + ((st == 2) ? 0 : st + 1) * STAGE_BYTES;
                ldsm_frags(0, Asn, 0);  // prefetch ks=0 of next kt -> buf 0
                mma_block(1);           // ks=3 (buf 1)
            } else {
                mma_block(1);
            }
            st  = (st  == 2) ? 0 : st  + 1;
            nst = (nst == 2) ? 0 : nst + 1;
        }

        CP_WAIT0();  // drain before smem reuse in next tile

        // Epilogue: out[r][c] = (acc + bias[c]) * s + shc * rowsum[r]
        const int gr0 = by * BM + warp_m * 64 + (lane >> 2);
        const int gc0 = bx * BN + warp_n * 64 + (lane & 3) * 2;
        #pragma unroll
        for (int mb = 0; mb < 4; mb++) {
            const int r0 = gr0 + mb * 16, r1 = r0 + 8;
            const float sh0 = shc * g_rowsum[r0];
            const float sh1 = shc * g_rowsum[r1];
            float* o0 = out + ((size_t)r0 << 12);
            float* o1 = out + ((size_t)r1 << 12);
            #pragma unroll
            for (int nb = 0; nb < 8; nb++) {
                const int gc = gc0 + nb * 8;
                const float bv0 = bias[gc], bv1 = bias[gc + 1];
                float2 v0, v1;
                v0.x = fmaf(acc[mb][nb][0] + bv0, s, sh0);
                v0.y = fmaf(acc[mb][nb][1] + bv1, s, sh0);
                v1.x = fmaf(acc[mb][nb][2] + bv0, s, sh1);
                v1.y = fmaf(acc[mb][nb][3] + bv1, s, sh1);
                *reinterpret_cast<float2*>(o0 + gc) = v0;
                *reinterpret_cast<float2*>(o1 + gc) = v1;
            }
        }
        __syncthreads();  // all warps done before next tile's loads
    }

    // Reset min/max accumulators for the next kernel_launch call
    if (blockIdx.x == 0 && tid == 0) {
        g_xmin_e = 0xFFFFFFFFu; g_xmax_e = 0u;
        g_wmin_e = 0xFFFFFFFFu; g_wmax_e = 0u;
    }
}

// ============================================================================
extern "C" void kernel_launch(void* const* d_in, const int* in_sizes, int n_in,
                              void* d_out, int out_size) {
    (void)in_sizes; (void)n_in; (void)out_size;
    const float* x    = (const float*)d_in[0];
    const float* w    = (const float*)d_in[1];
    const float* bias = (const float*)d_in[2];
    float* out = (float*)d_out;

    reduce_kernel<<<DIM, 256>>>(x, w);                            // launch 1
    finalize_kernel<<<1, 32>>>();                                 // launch 2
    quant_kernel<<<dim3(DIM * DIM / (8 * 256), 2), 256>>>(x, w);  // launch 3
    cudaFuncSetAttribute(gemm_kernel, cudaFuncAttributeMaxDynamicSharedMemorySize, SMEM_TOTAL);
    gemm_kernel<<<GRID_PERSIST, 128, SMEM_TOTAL>>>(bias, out);    // launch 4
}

// round 15
// speedup vs baseline: 1.3743x; 1.0606x over previous
#include <cuda_runtime.h>
#include <cuda_fp16.h>
#include <cstdint>
#include <cstddef>

// ============================================================================
// QUIK quantized linear, B = in = out = 4096.
//   x_q = trunc(clip((x - min(x))/((max-min)/8) - 4, -4, 3))   (global affine)
//   w_q likewise; out[i,j] = (x_q[i,:]·w_q[j,:] + bias[j])*s_a*s_w
//                            + (zero_a + 4*s_a)*rowsum_w[i]    (note index i)
// R15: kt unrolled x3 (compile-time stage indices, no SEL chains) + barrier
// hoisted before mma_block(2) so 2 MMA blocks absorb inter-warp skew.
// ============================================================================

#define DIM 4096
#define BM 128
#define BN 128
#define BK 64             // f16 elements per k-tile = 128 bytes per row
#define NITER (DIM / BK)  // 64
#define NTILES ((DIM / BM) * (DIM / BN))   // 1024
#define GRID_PERSIST 296                   // 2 CTAs x 148 SMs
#define STAGES 3
#define STAGE_BYTES (2 * BM * 128)         // A(16K) + B(16K) = 32768
#define SMEM_TOTAL (STAGES * STAGE_BYTES)  // 98304

// ---------------- device scratch (allocation-free rule) ---------------------
__device__ unsigned g_xmin_e = 0xFFFFFFFFu, g_xmax_e = 0u;
__device__ unsigned g_wmin_e = 0xFFFFFFFFu, g_wmax_e = 0u;
__device__ float g_rowsum[DIM];
__device__ float g_consts[8];  // 0:s=sa*sw 1:shiftc 2:x_zero 3:x_scale 4:w_zero 5:w_scale
__device__ unsigned short g_xqh[(size_t)DIM * DIM];  // f16 bits of quantized x
__device__ unsigned short g_wqh[(size_t)DIM * DIM];  // f16 bits of quantized w

// ---------------- PTX helpers (plain-sm80/75 features only) -----------------
__device__ __forceinline__ uint32_t smem_to_u32(const void* p) {
    uint32_t a;
    asm("{ .reg .u64 t; cvta.to.shared.u64 t, %1; cvt.u32.u64 %0, t; }" : "=r"(a) : "l"(p));
    return a;
}

#define CP_ASYNC16(saddr, gptr)                                              \
    asm volatile("cp.async.cg.shared.global [%0], [%1], 16;"                 \
                 :: "r"(saddr), "l"(gptr) : "memory")
#define CP_COMMIT() asm volatile("cp.async.commit_group;" ::: "memory")
#define CP_WAIT1()  asm volatile("cp.async.wait_group 1;" ::: "memory")
#define CP_WAIT0()  asm volatile("cp.async.wait_group 0;" ::: "memory")

#define LDSM_X4(r, addr)                                                     \
    asm volatile("ldmatrix.sync.aligned.m8n8.x4.shared.b16 {%0,%1,%2,%3}, [%4];" \
                 : "=r"((r)[0]), "=r"((r)[1]), "=r"((r)[2]), "=r"((r)[3])    \
                 : "r"(addr))

// f16 HMMA, f32 accumulate: D(16x8) += A(16x16) * B(16x8)
#define MMA_F16(c, a, b0v, b1v)                                              \
    asm volatile("mma.sync.aligned.m16n8k16.row.col.f32.f16.f16.f32 "        \
                 "{%0,%1,%2,%3}, {%4,%5,%6,%7}, {%8,%9}, {%0,%1,%2,%3};"     \
                 : "+f"((c)[0]), "+f"((c)[1]), "+f"((c)[2]), "+f"((c)[3])    \
                 : "r"((a)[0]), "r"((a)[1]), "r"((a)[2]), "r"((a)[3]),       \
                   "r"(b0v), "r"(b1v))

// Monotone float<->uint encoding for atomic min/max on fp32
__device__ __forceinline__ unsigned fenc(float f) {
    unsigned u = __float_as_uint(f);
    return (u & 0x80000000u) ? ~u : (u | 0x80000000u);
}
__device__ __forceinline__ float fdec(unsigned e) {
    return (e & 0x80000000u) ? __uint_as_float(e & 0x7FFFFFFFu) : __uint_as_float(~e);
}

// ============================================================================
// Launch 1: per-row pass — global min/max of x and w, weight row sums
// ============================================================================
__global__ void __launch_bounds__(256) reduce_kernel(const float* __restrict__ x,
                                                     const float* __restrict__ w) {
    const int row = blockIdx.x, tid = threadIdx.x;
    const float4* xr = reinterpret_cast<const float4*>(x + ((size_t)row << 12));
    const float4* wr = reinterpret_cast<const float4*>(w + ((size_t)row << 12));
    float xmn = 3.4e38f, xmx = -3.4e38f, wmn = 3.4e38f, wmx = -3.4e38f, ws = 0.0f;
    for (int i = tid; i < 1024; i += 256) {
        float4 a = xr[i];
        xmn = fminf(xmn, fminf(fminf(a.x, a.y), fminf(a.z, a.w)));
        xmx = fmaxf(xmx, fmaxf(fmaxf(a.x, a.y), fmaxf(a.z, a.w)));
        float4 b = wr[i];
        wmn = fminf(wmn, fminf(fminf(b.x, b.y), fminf(b.z, b.w)));
        wmx = fmaxf(wmx, fmaxf(fmaxf(b.x, b.y), fmaxf(b.z, b.w)));
        ws += (b.x + b.y) + (b.z + b.w);
    }
    #pragma unroll
    for (int o = 16; o; o >>= 1) {
        xmn = fminf(xmn, __shfl_xor_sync(0xFFFFFFFFu, xmn, o));
        xmx = fmaxf(xmx, __shfl_xor_sync(0xFFFFFFFFu, xmx, o));
        wmn = fminf(wmn, __shfl_xor_sync(0xFFFFFFFFu, wmn, o));
        wmx = fmaxf(wmx, __shfl_xor_sync(0xFFFFFFFFu, wmx, o));
        ws += __shfl_xor_sync(0xFFFFFFFFu, ws, o);
    }
    __shared__ float s_xmn[8], s_xmx[8], s_wmn[8], s_wmx[8], s_ws[8];
    const int wid = tid >> 5, lane = tid & 31;
    if (lane == 0) { s_xmn[wid] = xmn; s_xmx[wid] = xmx; s_wmn[wid] = wmn; s_wmx[wid] = wmx; s_ws[wid] = ws; }
    __syncthreads();
    if (tid == 0) {
        float a = s_xmn[0], b = s_xmx[0], c = s_wmn[0], d = s_wmx[0], e = s_ws[0];
        #pragma unroll
        for (int i = 1; i < 8; i++) {
            a = fminf(a, s_xmn[i]); b = fmaxf(b, s_xmx[i]);
            c = fminf(c, s_wmn[i]); d = fmaxf(d, s_wmx[i]);
            e += s_ws[i];
        }
        atomicMin(&g_xmin_e, fenc(a)); atomicMax(&g_xmax_e, fenc(b));
        atomicMin(&g_wmin_e, fenc(c)); atomicMax(&g_wmax_e, fenc(d));
        g_rowsum[row] = e;
    }
}

// ============================================================================
// Launch 2: scalar constants
// ============================================================================
__global__ void finalize_kernel() {
    if (threadIdx.x == 0) {
        float xmin = fdec(g_xmin_e), xmax = fdec(g_xmax_e);
        float wmin = fdec(g_wmin_e), wmax = fdec(g_wmax_e);
        float sa = (xmax - xmin) * 0.125f;  // /8 exact
        float sw = (wmax - wmin) * 0.125f;
        g_consts[0] = sa * sw;
        g_consts[1] = xmin + 4.0f * sa;
        g_consts[2] = xmin; g_consts[3] = sa;
        g_consts[4] = wmin; g_consts[5] = sw;
    }
}

// ============================================================================
// Launch 3: quantize BOTH matrices to f16 scratch (blockIdx.y: 0=x, 1=w).
// ============================================================================
__global__ void __launch_bounds__(256) quant_kernel(const float* __restrict__ x,
                                                    const float* __restrict__ w) {
    const int which = blockIdx.y;
    const float zero  = which ? g_consts[4] : g_consts[2];
    const float scale = which ? g_consts[5] : g_consts[3];
    const float* src = which ? w : x;
    unsigned short* dst = which ? g_wqh : g_xqh;
    const size_t i = ((size_t)blockIdx.x * 256 + threadIdx.x) * 8;
    const float4* s4 = reinterpret_cast<const float4*>(src + i);
    float4 a = s4[0], b = s4[1];
    float v[8] = {a.x, a.y, a.z, a.w, b.x, b.y, b.z, b.w};
    unsigned r[4];
    #pragma unroll
    for (int k = 0; k < 4; k++) {
        float q0 = fminf(fmaxf(__fdiv_rn(v[2 * k] - zero, scale) - 4.0f, -4.0f), 3.0f);
        float q1 = fminf(fmaxf(__fdiv_rn(v[2 * k + 1] - zero, scale) - 4.0f, -4.0f), 3.0f);
        unsigned lo = __half_as_ushort(__float2half_rn((float)(int)q0));
        unsigned hi = __half_as_ushort(__float2half_rn((float)(int)q1));
        r[k] = lo | (hi << 16);
    }
    *reinterpret_cast<uint4*>(dst + i) = make_uint4(r[0], r[1], r[2], r[3]);
}

// ============================================================================
// Launch 4 (ncu-captured slot): persistent f16 HMMA GEMM, f32 accumulate,
// register fragment double-buffering, kt unrolled x3 (constant stage idx),
// barrier hoisted before mma_block(2). 128 threads = 4 warps (2x2), warp
// tile 64x64; block tile 128x128; BK=64; 3-stage cp.async pipeline.
// ============================================================================
__global__ void __launch_bounds__(128, 2) gemm_kernel(const float* __restrict__ bias,
                                                      float* __restrict__ out) {
    extern __shared__ char smem[];
    const int tid = threadIdx.x, lane = tid & 31, wid = tid >> 5;
    const int warp_m = wid >> 1, warp_n = wid & 1;   // 2 x 2 warp grid
    const uint32_t sm0 = smem_to_u32(smem);

    // copy-loop: 2048 16B-chunks per stage; 16 per thread
    const int cp_rc = tid >> 3;            // 0..15
    const int cp_c  = tid & 7;
    const uint32_t cp_sbase = (uint32_t)(cp_rc * 128 + ((cp_c ^ (cp_rc & 7)) << 4));
    const uint32_t cp_gbase = ((uint32_t)cp_rc << 13) + ((uint32_t)cp_c << 4);

    const int a_row  = warp_m * 64 + (lane & 7) + ((lane >> 3) & 1) * 8;
    const int a_kbit = (lane >> 4) & 1;
    const int a_xor  = a_row & 7;
    uint32_t a_rowoff[4];
    #pragma unroll
    for (int mb = 0; mb < 4; mb++) a_rowoff[mb] = (uint32_t)(a_row + mb * 16) * 128;

    const int b_col  = warp_n * 64 + (lane & 7) + ((lane >> 3) & 1) * 8;
    const int b_kbit = (lane >> 4) & 1;
    const int b_xor  = b_col & 7;
    uint32_t b_rowoff[4];
    #pragma unroll
    for (int h = 0; h < 4; h++) b_rowoff[h] = (uint32_t)(b_col + h * 16) * 128;

    uint32_t ac_k[4], bc_k[4];
    #pragma unroll
    for (int ks = 0; ks < 4; ks++) {
        ac_k[ks] = (uint32_t)(((2 * ks + a_kbit) ^ a_xor) << 4);
        bc_k[ks] = (uint32_t)(((2 * ks + b_kbit) ^ b_xor) << 4);
    }

    const float s = g_consts[0], shc = g_consts[1];

    uint32_t Af[2][4][4], Bff[2][4][4];  // double-buffered fragments

    #pragma unroll 1
    for (int tile = blockIdx.x; tile < NTILES; tile += GRID_PERSIST) {
        const int by = tile >> 5, bx = tile & 31;
        const unsigned short* Agbase = g_xqh + ((size_t)(by * BM) << 12);
        const unsigned short* Bgbase = g_wqh + ((size_t)(bx * BN) << 12);

        float acc[4][8][4];
        #pragma unroll
        for (int mb = 0; mb < 4; mb++)
            #pragma unroll
            for (int nb = 0; nb < 8; nb++)
                #pragma unroll
                for (int e = 0; e < 4; e++) acc[mb][nb][e] = 0.0f;

        auto load_stage = [&](int kt, uint32_t As) {
            const uint32_t Bs = As + BM * 128;
            const char* Ag = reinterpret_cast<const char*>(Agbase + (size_t)kt * BK) + cp_gbase;
            const char* Bg = reinterpret_cast<const char*>(Bgbase + (size_t)kt * BK) + cp_gbase;
            #pragma unroll
            for (int i = 0; i < 8; i++) {
                CP_ASYNC16(As + cp_sbase + i * 2048, Ag + i * (size_t)131072);
                CP_ASYNC16(Bs + cp_sbase + i * 2048, Bg + i * (size_t)131072);
            }
        };
        auto ldsm_frags = [&](int buf, uint32_t As, int ks) {
            const uint32_t Bs = As + BM * 128;
            #pragma unroll
            for (int mb = 0; mb < 4; mb++) LDSM_X4(Af[buf][mb],  As + a_rowoff[mb] + ac_k[ks]);
            #pragma unroll
            for (int h = 0; h < 4; h++)    LDSM_X4(Bff[buf][h],  Bs + b_rowoff[h] + bc_k[ks]);
        };
        auto mma_block = [&](int buf) {
            #pragma unroll
            for (int mb = 0; mb < 4; mb++)
                #pragma unroll
                for (int h = 0; h < 4; h++) {
                    MMA_F16(acc[mb][2 * h],     Af[buf][mb], Bff[buf][h][0], Bff[buf][h][2]);
                    MMA_F16(acc[mb][2 * h + 1], Af[buf][mb], Bff[buf][h][1], Bff[buf][h][3]);
                }
        };
        // One kt iteration with compile-time stage addresses.
        // Barrier placed right after the last read of the current stage
        // (ks=3 fragment prefetch), BEFORE mma_block(2): two MMA blocks
        // (~512 tensor-cyc) then cover inter-warp skew.
        auto iteration = [&](int kt, uint32_t As, uint32_t Asn, uint32_t Asl) {
            if (kt + 2 < NITER) load_stage(kt + 2, Asl);
            CP_COMMIT();
            ldsm_frags(1, As, 1);
            mma_block(0);
            ldsm_frags(0, As, 2);
            mma_block(1);
            ldsm_frags(1, As, 3);          // last read of current stage
            if (kt + 1 < NITER) {
                CP_WAIT1();                 // next stage resident
                __syncthreads();            // stage (kt)%3 now safe to overwrite
                mma_block(0);               // ks=2
                ldsm_frags(0, Asn, 0);      // ks=0 of next kt
                mma_block(1);               // ks=3
            } else {
                mma_block(0);
                mma_block(1);
            }
        };

        const uint32_t S0 = sm0, S1 = sm0 + STAGE_BYTES, S2 = sm0 + 2 * STAGE_BYTES;
        load_stage(0, S0); CP_COMMIT();
        load_stage(1, S1); CP_COMMIT();
        CP_WAIT1();
        __syncthreads();
        ldsm_frags(0, S0, 0);

        #pragma unroll 1
        for (int kt3 = 0; kt3 < NITER / 3; kt3++) {   // 21 x 3 = 63
            iteration(kt3 * 3,     S0, S1, S2);
            iteration(kt3 * 3 + 1, S1, S2, S0);
            iteration(kt3 * 3 + 2, S2, S0, S1);
        }
        iteration(63, S0, S1, S2);                    // 63 % 3 == 0

        CP_WAIT0();  // drain before smem reuse in next tile

        // Epilogue: out[r][c] = (acc + bias[c]) * s + shc * rowsum[r]
        const int gr0 = by * BM + warp_m * 64 + (lane >> 2);
        const int gc0 = bx * BN + warp_n * 64 + (lane & 3) * 2;
        #pragma unroll
        for (int mb = 0; mb < 4; mb++) {
            const int r0 = gr0 + mb * 16, r1 = r0 + 8;
            const float sh0 = shc * g_rowsum[r0];
            const float sh1 = shc * g_rowsum[r1];
            float* o0 = out + ((size_t)r0 << 12);
            float* o1 = out + ((size_t)r1 << 12);
            #pragma unroll
            for (int nb = 0; nb < 8; nb++) {
                const int gc = gc0 + nb * 8;
                const float bv0 = bias[gc], bv1 = bias[gc + 1];
                float2 v0, v1;
                v0.x = fmaf(acc[mb][nb][0] + bv0, s, sh0);
                v0.y = fmaf(acc[mb][nb][1] + bv1, s, sh0);
                v1.x = fmaf(acc[mb][nb][2] + bv0, s, sh1);
                v1.y = fmaf(acc[mb][nb][3] + bv1, s, sh1);
                *reinterpret_cast<float2*>(o0 + gc) = v0;
                *reinterpret_cast<float2*>(o1 + gc) = v1;
            }
        }
        __syncthreads();  // all warps done before next tile's loads
    }

    // Reset min/max accumulators for the next kernel_launch call
    if (blockIdx.x == 0 && tid == 0) {
        g_xmin_e = 0xFFFFFFFFu; g_xmax_e = 0u;
        g_wmin_e = 0xFFFFFFFFu; g_wmax_e = 0u;
    }
}

// ============================================================================
extern "C" void kernel_launch(void* const* d_in, const int* in_sizes, int n_in,
                              void* d_out, int out_size) {
    (void)in_sizes; (void)n_in; (void)out_size;
    const float* x    = (const float*)d_in[0];
    const float* w    = (const float*)d_in[1];
    const float* bias = (const float*)d_in[2];
    float* out = (float*)d_out;

    reduce_kernel<<<DIM, 256>>>(x, w);                            // launch 1
    finalize_kernel<<<1, 32>>>();                                 // launch 2
    quant_kernel<<<dim3(DIM * DIM / (8 * 256), 2), 256>>>(x, w);  // launch 3
    cudaFuncSetAttribute(gemm_kernel, cudaFuncAttributeMaxDynamicSharedMemorySize, SMEM_TOTAL);
    gemm_kernel<<<GRID_PERSIST, 128, SMEM_TOTAL>>>(bias, out);    // launch 4
}